// round 4
// baseline (speedup 1.0000x reference)
#include <cuda_runtime.h>
#include <math.h>

#define NN 100000
#define NE 1600000
#define ESL (NE + NN)
#define NGRAPH 64
#define NEG 0.2f

// ---------------- scratch (device globals; no allocation) ----------------
__device__ float    d_cnt[NN];
__device__ float    d_mean[NN * 8];
__device__ float    d_xp[NN * 64];
__device__ float    d_als[NN * 4];
__device__ float    d_ald[NN * 4];
__device__ float    d_h0[NN * 64];
__device__ float    d_h1[NN * 64];
__device__ float    d_pool[NGRAPH * 64];
__device__ float    d_gcnt[NGRAPH];
__device__ float    d_weatt[3 * 32];            // all 3 layers precomputed
// CSR
__device__ int      d_roff[NN + 1];
__device__ int      d_cur[NN];
__device__ int      d_csrc[ESL];                // src node per CSR slot
__device__ float    d_ea_csr[(size_t)ESL * 8];  // edge attrs in CSR order

// ---------------- helpers ----------------
__device__ __forceinline__ void red2(float* p, float a, float b) {
    asm volatile("red.global.add.v2.f32 [%0], {%1, %2};" :: "l"(p), "f"(a), "f"(b) : "memory");
}

// ---------------- self-loop mean edge-attr (sum) + in-degree count ----------------
__global__ void k_count(const int* __restrict__ dst, const float* __restrict__ ea) {
    int e = blockIdx.x * blockDim.x + threadIdx.x;
    if (e >= NE) return;
    int dd = dst[e];
    atomicAdd(&d_cnt[dd], 1.0f);
#pragma unroll
    for (int d = 0; d < 8; d += 2)
        red2(&d_mean[dd * 8 + d], ea[(size_t)e * 8 + d], ea[(size_t)e * 8 + d + 1]);
}

// ---------------- CSR offsets: deg[n] = cnt[n] + 1 (self loop); exclusive scan ----------------
__global__ void k_scan() {
    __shared__ int ssum[1024];
    const int CH = (NN + 1023) / 1024;
    int t = threadIdx.x;
    int base = t * CH;
    int s = 0;
    for (int i = 0; i < CH; i++) {
        int idx = base + i;
        if (idx < NN) s += (int)(d_cnt[idx] + 0.5f) + 1;
    }
    ssum[t] = s;
    __syncthreads();
    for (int off = 1; off < 1024; off <<= 1) {
        int v = (t >= off) ? ssum[t - off] : 0;
        __syncthreads();
        ssum[t] += v;
        __syncthreads();
    }
    int run = (t == 0) ? 0 : ssum[t - 1];
    for (int i = 0; i < CH; i++) {
        int idx = base + i;
        if (idx < NN) {
            d_roff[idx] = run;
            d_cur[idx] = run;
            run += (int)(d_cnt[idx] + 0.5f) + 1;
        }
    }
    if (t == 1023) d_roff[NN] = ESL;
}

// ---------------- CSR fill: src ids + permuted edge attrs (self-loop rows get mean) ----------------
__global__ void k_fill(const int* __restrict__ src, const int* __restrict__ dst,
                       const float* __restrict__ ea) {
    int e = blockIdx.x * blockDim.x + threadIdx.x;
    if (e >= ESL) return;
    int s, dd;
    float4 a0, a1;
    if (e < NE) {
        s = src[e]; dd = dst[e];
        const float4* a = (const float4*)(ea + (size_t)e * 8);
        a0 = a[0]; a1 = a[1];
    } else {
        s = dd = e - NE;
        const float4* a = (const float4*)(d_mean + (size_t)(e - NE) * 8);
        a0 = a[0]; a1 = a[1];
        float ic = 1.0f / fmaxf(d_cnt[dd], 1.0f);
        a0.x *= ic; a0.y *= ic; a0.z *= ic; a0.w *= ic;
        a1.x *= ic; a1.y *= ic; a1.z *= ic; a1.w *= ic;
    }
    int pos = atomicAdd(&d_cur[dd], 1);
    d_csrc[pos] = s;
    float4* o = (float4*)(d_ea_csr + (size_t)pos * 8);
    o[0] = a0; o[1] = a1;
}

// ---------------- all-layer edge-attention weights: weatt[l][d][h] ----------------
__global__ void k_weatt(const float* __restrict__ We0, const float* __restrict__ ae0,
                        const float* __restrict__ Weh, const float* __restrict__ aeh) {
    int t = threadIdx.x;
    if (t >= 96) return;
    int l = t >> 5, r = t & 31;
    int d = r >> 2, h = r & 3;
    const float* We = (l == 0) ? We0 : (Weh + (l - 1) * 512);
    const float* ae = (l == 0) ? ae0 : (aeh + (l - 1) * 64);
    float s = 0.0f;
#pragma unroll
    for (int c = 0; c < 16; c++) s += We[d * 64 + h * 16 + c] * ae[h * 16 + c];
    d_weatt[l * 32 + d * 4 + h] = s;
}

// ---------------- projection: xp = X @ W ; al_s/al_d per (node, head)
// 256 threads = 32 nodes x 8 col-groups; thread computes 8 output cols of 1 node.
__global__ void k_project(const float* __restrict__ X, int fin, const float* __restrict__ W,
                          const float* __restrict__ as_, const float* __restrict__ ad_) {
    __shared__ float sW[64 * 64];
    __shared__ float sx[32 * 65];     // padded stride kills bank conflicts
    __shared__ float sa[64], sd[64];
    int tid = threadIdx.x;
    for (int i = tid; i < fin * 64; i += 256) sW[i] = W[i];
    if (tid < 64) { sa[tid] = as_[tid]; sd[tid] = ad_[tid]; }
    int lf = (fin == 64) ? 6 : 5;
    int fmask = fin - 1;
    // load 32 node rows (coalesced from X) into padded smem
    int base = blockIdx.x * 32;
    for (int i = tid; i < 32 * fin; i += 256) {
        int nl = i >> lf, c = i & fmask;
        sx[nl * 65 + c] = X[(size_t)base * fin + i];
    }
    __syncthreads();

    int nl = tid >> 3;          // local node 0..31
    int cg = tid & 7;           // col group: cols [cg*8, cg*8+8)
    int n = base + nl;
    float acc[8] = {0, 0, 0, 0, 0, 0, 0, 0};
    const float* xr = sx + nl * 65;
    for (int i = 0; i < fin; i++) {
        float xv = xr[i];
        float4 w0 = *(const float4*)(sW + i * 64 + cg * 8);
        float4 w1 = *(const float4*)(sW + i * 64 + cg * 8 + 4);
        acc[0] += xv * w0.x; acc[1] += xv * w0.y; acc[2] += xv * w0.z; acc[3] += xv * w0.w;
        acc[4] += xv * w1.x; acc[5] += xv * w1.y; acc[6] += xv * w1.z; acc[7] += xv * w1.w;
    }
    // store xp (two 16B stores, coalesced across cg)
    float4* xo = (float4*)(d_xp + (size_t)n * 64 + cg * 8);
    xo[0] = make_float4(acc[0], acc[1], acc[2], acc[3]);
    xo[1] = make_float4(acc[4], acc[5], acc[6], acc[7]);
    // attention logits: head h = cg>>1; partner col-group is cg^1 (same head)
    float ps = 0.0f, pd = 0.0f;
#pragma unroll
    for (int j = 0; j < 8; j++) {
        ps += acc[j] * sa[cg * 8 + j];
        pd += acc[j] * sd[cg * 8 + j];
    }
    ps += __shfl_xor_sync(0xffffffffu, ps, 1);
    pd += __shfl_xor_sync(0xffffffffu, pd, 1);
    if ((cg & 1) == 0) {
        int h = cg >> 1;
        d_als[n * 4 + h] = ps;
        d_ald[n * 4 + h] = pd;
    }
}

// ---------------- fully fused single-pass (online softmax):
// logits + leaky-relu + running max + exp + aggregate + bias. warp per dst node.
__global__ void k_agg(const float* __restrict__ weatt, const float* __restrict__ b,
                      int dorelu, float* __restrict__ out) {
    __shared__ float sw[32];
    int tid = threadIdx.x;
    if (tid < 32) sw[tid] = weatt[tid];
    __syncthreads();
    int warp = (blockIdx.x * blockDim.x + tid) >> 5;
    if (warp >= NN) return;
    int lane = tid & 31;
    int h = lane >> 3, sub = lane & 7;
    int beg = d_roff[warp];
    int end = d_roff[warp + 1];
    float ald_h = d_ald[warp * 4 + h];
    float wd[8];
#pragma unroll
    for (int d = 0; d < 8; d++) wd[d] = sw[d * 4 + h];

    float mx = -INFINITY, den = 0.0f, a0 = 0.0f, a1 = 0.0f;
    for (int p0 = beg; p0 < end; p0 += 8) {
        int myp = p0 + sub;
        float al = -INFINITY;
        int s = 0;
        if (myp < end) {
            s = d_csrc[myp];
            const float4* ap = (const float4*)(d_ea_csr + (size_t)myp * 8);
            float4 e0 = ap[0], e1 = ap[1];
            float ale = e0.x * wd[0] + e0.y * wd[1] + e0.z * wd[2] + e0.w * wd[3]
                      + e1.x * wd[4] + e1.y * wd[5] + e1.z * wd[6] + e1.w * wd[7];
            float a = d_als[s * 4 + h] + ald_h + ale;
            al = a > 0.0f ? a : NEG * a;
        }
        // batch max within the 8-lane head group
        float bmx = al;
#pragma unroll
        for (int off = 4; off; off >>= 1)
            bmx = fmaxf(bmx, __shfl_xor_sync(0xffffffffu, bmx, off));
        float nmx = fmaxf(mx, bmx);
        float scale = __expf(mx - nmx);       // first iter: exp(-inf - finite) = 0
        den *= scale; a0 *= scale; a1 *= scale;
        float c = __expf(al - nmx);           // invalid lanes: exp(-inf) = 0
        mx = nmx;

        int nb = end - p0;
        if (nb >= 8) {
#pragma unroll
            for (int j = 0; j < 8; j++) {
                float cj = __shfl_sync(0xffffffffu, c, h * 8 + j);
                int   sj = __shfl_sync(0xffffffffu, s, j);
                float2 v = *(const float2*)(d_xp + (size_t)sj * 64 + lane * 2);
                den += cj; a0 += cj * v.x; a1 += cj * v.y;
            }
        } else {
            for (int j = 0; j < nb; j++) {
                float cj = __shfl_sync(0xffffffffu, c, h * 8 + j);
                int   sj = __shfl_sync(0xffffffffu, s, j);
                float2 v = *(const float2*)(d_xp + (size_t)sj * 64 + lane * 2);
                den += cj; a0 += cj * v.x; a1 += cj * v.y;
            }
        }
    }
    float inv = 1.0f / (den + 1e-16f);
    float o0 = a0 * inv + b[lane * 2];
    float o1 = a1 * inv + b[lane * 2 + 1];
    if (dorelu) { o0 = fmaxf(o0, 0.0f); o1 = fmaxf(o1, 0.0f); }
    *(float2*)(out + (size_t)warp * 64 + lane * 2) = make_float2(o0, o1);
}

// ---------------- global mean pool ----------------
__global__ void k_pool(const int* __restrict__ batch, const float* __restrict__ h) {
    size_t t = (size_t)blockIdx.x * blockDim.x + threadIdx.x;
    int n = (int)(t >> 5);
    if (n >= NN) return;
    int c2 = (int)(t & 31) * 2;
    int g = batch[n];
    red2(&d_pool[g * 64 + c2], h[(size_t)n * 64 + c2], h[(size_t)n * 64 + c2 + 1]);
    if (c2 == 0) atomicAdd(&d_gcnt[g], 1.0f);
}

// ---------------- MLP head ----------------
__global__ void k_mlp(const float* __restrict__ fc1w, const float* __restrict__ fc1b,
                      const float* __restrict__ fc2w, const float* __restrict__ fc2b,
                      float* __restrict__ out) {
    int g = threadIdx.x;
    if (g >= NGRAPH) return;
    float ic = 1.0f / fmaxf(d_gcnt[g], 1.0f);
    float hr[64];
#pragma unroll
    for (int c = 0; c < 64; c++) hr[c] = d_pool[g * 64 + c] * ic;
    float y1[32];
#pragma unroll
    for (int j = 0; j < 32; j++) {
        float s = fc1b[j];
#pragma unroll
        for (int c = 0; c < 64; c++) s += hr[c] * fc1w[c * 32 + j];
        y1[j] = fmaxf(s, 0.0f);
    }
#pragma unroll
    for (int o = 0; o < 2; o++) {
        float s = fc2b[o];
#pragma unroll
        for (int j = 0; j < 32; j++) s += y1[j] * fc2w[j * 2 + o];
        out[g * 2 + o] = s;
    }
}

// ---------------- host ----------------
extern "C" void kernel_launch(void* const* d_in, const int* in_sizes, int n_in,
                              void* d_out, int out_size) {
    (void)in_sizes; (void)n_in; (void)out_size;
    const float* x    = (const float*)d_in[0];
    const int*   ei   = (const int*)d_in[1];
    const float* ea   = (const float*)d_in[2];
    const int*   batch= (const int*)d_in[3];
    const float* W0   = (const float*)d_in[4];
    const float* as0  = (const float*)d_in[5];
    const float* ad0  = (const float*)d_in[6];
    const float* We0  = (const float*)d_in[7];
    const float* ae0  = (const float*)d_in[8];
    const float* b0   = (const float*)d_in[9];
    const float* Wh   = (const float*)d_in[10];
    const float* ash  = (const float*)d_in[11];
    const float* adh  = (const float*)d_in[12];
    const float* Weh  = (const float*)d_in[13];
    const float* aeh  = (const float*)d_in[14];
    const float* bh   = (const float*)d_in[15];
    const float* fc1w = (const float*)d_in[16];
    const float* fc1b = (const float*)d_in[17];
    const float* fc2w = (const float*)d_in[18];
    const float* fc2b = (const float*)d_in[19];
    float* out = (float*)d_out;

    const int* src = ei;
    const int* dst = ei + NE;

    void *p_cnt, *p_mean, *p_h0, *p_h1, *p_pool, *p_gcnt, *p_weatt;
    cudaGetSymbolAddress(&p_cnt,  d_cnt);
    cudaGetSymbolAddress(&p_mean, d_mean);
    cudaGetSymbolAddress(&p_h0,   d_h0);
    cudaGetSymbolAddress(&p_h1,   d_h1);
    cudaGetSymbolAddress(&p_pool, d_pool);
    cudaGetSymbolAddress(&p_gcnt, d_gcnt);
    cudaGetSymbolAddress(&p_weatt,d_weatt);

    // setup: degree count + self-loop mean attrs + CSR build (shared across layers)
    cudaMemsetAsync(p_cnt, 0, NN * sizeof(float));
    cudaMemsetAsync(p_mean, 0, NN * 8 * sizeof(float));
    k_count<<<(NE + 255) / 256, 256>>>(dst, ea);
    k_scan<<<1, 1024>>>();
    k_fill<<<(ESL + 255) / 256, 256>>>(src, dst, ea);
    k_weatt<<<1, 96>>>(We0, ae0, Weh, aeh);

    struct LayerCfg {
        const float* X; int fin; const float* W;
        const float* as; const float* ad; const float* b; float* hout; int relu;
    };
    LayerCfg L[3] = {
        { x,            32, W0,        as0,      ad0,      b0,      (float*)p_h0, 1 },
        { (float*)p_h0, 64, Wh,        ash,      adh,      bh,      (float*)p_h1, 0 },
        { (float*)p_h1, 64, Wh + 4096, ash + 64, adh + 64, bh + 64, (float*)p_h0, 0 },
    };

    for (int l = 0; l < 3; l++) {
        k_project<<<NN / 32, 256>>>(L[l].X, L[l].fin, L[l].W, L[l].as, L[l].ad);
        k_agg<<<(NN * 32 + 255) / 256, 256>>>((const float*)p_weatt + l * 32,
                                              L[l].b, L[l].relu, L[l].hout);
    }

    cudaMemsetAsync(p_pool, 0, NGRAPH * 64 * sizeof(float));
    cudaMemsetAsync(p_gcnt, 0, NGRAPH * sizeof(float));
    k_pool<<<(int)(((size_t)NN * 32 + 255) / 256), 256>>>(batch, (const float*)p_h0);
    k_mlp<<<1, 64>>>(fc1w, fc1b, fc2w, fc2b, out);
}

// round 5
// speedup vs baseline: 1.0089x; 1.0089x over previous
#include <cuda_runtime.h>
#include <math.h>

#define NN 100000
#define NE 1600000
#define ESL (NE + NN)
#define NGRAPH 64
#define NEG 0.2f

// ---------------- scratch (device globals; no allocation) ----------------
__device__ float    d_cnt[NN];
__device__ float    d_mean[NN * 8];
__device__ float    d_xp[NN * 64];
__device__ float    d_als[NN * 4];
__device__ float    d_ald[NN * 4];
__device__ float    d_alpha[(size_t)ESL * 4];   // CSR order, coalesced
__device__ float    d_h0[NN * 64];
__device__ float    d_h1[NN * 64];
__device__ float    d_pool[NGRAPH * 64];
__device__ float    d_gcnt[NGRAPH];
__device__ float    d_weatt[3 * 32];            // all 3 layers precomputed
// CSR
__device__ int      d_roff[NN + 1];
__device__ int      d_cur[NN];
__device__ int      d_csrc[ESL];                // src node per CSR slot
__device__ float    d_ea_csr[(size_t)ESL * 8];  // edge attrs in CSR order

// ---------------- helpers ----------------
__device__ __forceinline__ void red2(float* p, float a, float b) {
    asm volatile("red.global.add.v2.f32 [%0], {%1, %2};" :: "l"(p), "f"(a), "f"(b) : "memory");
}

// ---------------- init: zero scratch + all-layer edge-attention weights ----------------
__global__ void k_init(const float* __restrict__ We0, const float* __restrict__ ae0,
                       const float* __restrict__ Weh, const float* __restrict__ aeh) {
    int stride = gridDim.x * blockDim.x;
    int t = blockIdx.x * blockDim.x + threadIdx.x;
    for (int i = t; i < NN; i += stride) d_cnt[i] = 0.0f;
    for (int i = t; i < NN * 8; i += stride) d_mean[i] = 0.0f;
    for (int i = t; i < NGRAPH * 64; i += stride) d_pool[i] = 0.0f;
    for (int i = t; i < NGRAPH; i += stride) d_gcnt[i] = 0.0f;
    if (t < 96) {
        int l = t >> 5, r = t & 31;
        int d = r >> 2, h = r & 3;
        const float* We = (l == 0) ? We0 : (Weh + (l - 1) * 512);
        const float* ae = (l == 0) ? ae0 : (aeh + (l - 1) * 64);
        float s = 0.0f;
#pragma unroll
        for (int c = 0; c < 16; c++) s += We[d * 64 + h * 16 + c] * ae[h * 16 + c];
        d_weatt[l * 32 + d * 4 + h] = s;
    }
}

// ---------------- self-loop mean edge-attr (sum) + in-degree count ----------------
__global__ void k_count(const int* __restrict__ dst, const float* __restrict__ ea) {
    int e = blockIdx.x * blockDim.x + threadIdx.x;
    if (e >= NE) return;
    int dd = dst[e];
    atomicAdd(&d_cnt[dd], 1.0f);
#pragma unroll
    for (int d = 0; d < 8; d += 2)
        red2(&d_mean[dd * 8 + d], ea[(size_t)e * 8 + d], ea[(size_t)e * 8 + d + 1]);
}

// ---------------- CSR offsets: deg[n] = cnt[n] + 1 (self loop); exclusive scan ----------------
__global__ void k_scan() {
    __shared__ int ssum[1024];
    const int CH = (NN + 1023) / 1024;
    int t = threadIdx.x;
    int base = t * CH;
    int s = 0;
    for (int i = 0; i < CH; i++) {
        int idx = base + i;
        if (idx < NN) s += (int)(d_cnt[idx] + 0.5f) + 1;
    }
    ssum[t] = s;
    __syncthreads();
    for (int off = 1; off < 1024; off <<= 1) {
        int v = (t >= off) ? ssum[t - off] : 0;
        __syncthreads();
        ssum[t] += v;
        __syncthreads();
    }
    int run = (t == 0) ? 0 : ssum[t - 1];
    for (int i = 0; i < CH; i++) {
        int idx = base + i;
        if (idx < NN) {
            d_roff[idx] = run;
            d_cur[idx] = run;
            run += (int)(d_cnt[idx] + 0.5f) + 1;
        }
    }
    if (t == 1023) d_roff[NN] = ESL;
}

// ---------------- CSR fill: src ids + permuted edge attrs (self-loop rows get mean) ----------------
__global__ void k_fill(const int* __restrict__ src, const int* __restrict__ dst,
                       const float* __restrict__ ea) {
    int e = blockIdx.x * blockDim.x + threadIdx.x;
    if (e >= ESL) return;
    int s, dd;
    float4 a0, a1;
    if (e < NE) {
        s = src[e]; dd = dst[e];
        const float4* a = (const float4*)(ea + (size_t)e * 8);
        a0 = a[0]; a1 = a[1];
    } else {
        s = dd = e - NE;
        const float4* a = (const float4*)(d_mean + (size_t)(e - NE) * 8);
        a0 = a[0]; a1 = a[1];
        float ic = 1.0f / fmaxf(d_cnt[dd], 1.0f);
        a0.x *= ic; a0.y *= ic; a0.z *= ic; a0.w *= ic;
        a1.x *= ic; a1.y *= ic; a1.z *= ic; a1.w *= ic;
    }
    int pos = atomicAdd(&d_cur[dd], 1);
    d_csrc[pos] = s;
    float4* o = (float4*)(d_ea_csr + (size_t)pos * 8);
    o[0] = a0; o[1] = a1;
}

// ---------------- projection: xp = X @ W ; al_s/al_d per (node, head)
// 256 threads = 32 nodes x 8 col-groups; thread computes 8 output cols of 1 node.
__global__ void k_project(const float* __restrict__ X, int fin, const float* __restrict__ W,
                          const float* __restrict__ as_, const float* __restrict__ ad_) {
    __shared__ float sW[64 * 64];
    __shared__ float sx[32 * 65];     // padded stride kills bank conflicts
    __shared__ float sa[64], sd[64];
    int tid = threadIdx.x;
    for (int i = tid; i < fin * 64; i += 256) sW[i] = W[i];
    if (tid < 64) { sa[tid] = as_[tid]; sd[tid] = ad_[tid]; }
    int lf = (fin == 64) ? 6 : 5;
    int fmask = fin - 1;
    int base = blockIdx.x * 32;
    for (int i = tid; i < 32 * fin; i += 256) {
        int nl = i >> lf, c = i & fmask;
        sx[nl * 65 + c] = X[(size_t)base * fin + i];
    }
    __syncthreads();

    int nl = tid >> 3;          // local node 0..31
    int cg = tid & 7;           // col group: cols [cg*8, cg*8+8)
    int n = base + nl;
    float acc[8] = {0, 0, 0, 0, 0, 0, 0, 0};
    const float* xr = sx + nl * 65;
    for (int i = 0; i < fin; i++) {
        float xv = xr[i];
        float4 w0 = *(const float4*)(sW + i * 64 + cg * 8);
        float4 w1 = *(const float4*)(sW + i * 64 + cg * 8 + 4);
        acc[0] += xv * w0.x; acc[1] += xv * w0.y; acc[2] += xv * w0.z; acc[3] += xv * w0.w;
        acc[4] += xv * w1.x; acc[5] += xv * w1.y; acc[6] += xv * w1.z; acc[7] += xv * w1.w;
    }
    float4* xo = (float4*)(d_xp + (size_t)n * 64 + cg * 8);
    xo[0] = make_float4(acc[0], acc[1], acc[2], acc[3]);
    xo[1] = make_float4(acc[4], acc[5], acc[6], acc[7]);
    float ps = 0.0f, pd = 0.0f;
#pragma unroll
    for (int j = 0; j < 8; j++) {
        ps += acc[j] * sa[cg * 8 + j];
        pd += acc[j] * sd[cg * 8 + j];
    }
    ps += __shfl_xor_sync(0xffffffffu, ps, 1);
    pd += __shfl_xor_sync(0xffffffffu, pd, 1);
    if ((cg & 1) == 0) {
        int h = cg >> 1;
        d_als[n * 4 + h] = ps;
        d_ald[n * 4 + h] = pd;
    }
}

// ---------------- fused two-pass softmax + aggregate + bias: warp per dst node ----------------
__global__ void k_agg(const float* __restrict__ weatt, const float* __restrict__ b,
                      int dorelu, float* __restrict__ out) {
    __shared__ float sw[32];
    int tid = threadIdx.x;
    if (tid < 32) sw[tid] = weatt[tid];
    __syncthreads();
    int warp = (blockIdx.x * blockDim.x + tid) >> 5;
    if (warp >= NN) return;
    int lane = tid & 31;
    int h = lane >> 3, sub = lane & 7;
    int beg = d_roff[warp];
    int end = d_roff[warp + 1];
    float ald_h = d_ald[warp * 4 + h];
    float wd[8];
#pragma unroll
    for (int d = 0; d < 8; d++) wd[d] = sw[d * 4 + h];

    // ---- pass A: alpha per (edge, head), running max in registers ----
    float mx = -INFINITY;
    for (int p0 = beg; p0 < end; p0 += 8) {
        int myp = p0 + sub;
        float al = -INFINITY;
        if (myp < end) {
            int s = d_csrc[myp];
            const float4* ap = (const float4*)(d_ea_csr + (size_t)myp * 8);
            float4 e0 = ap[0], e1 = ap[1];
            float ale = e0.x * wd[0] + e0.y * wd[1] + e0.z * wd[2] + e0.w * wd[3]
                      + e1.x * wd[4] + e1.y * wd[5] + e1.z * wd[6] + e1.w * wd[7];
            float a = d_als[s * 4 + h] + ald_h + ale;
            al = a > 0.0f ? a : NEG * a;
            d_alpha[(size_t)myp * 4 + h] = al;   // coalesced 128B per warp batch
        }
        mx = fmaxf(mx, al);
    }
#pragma unroll
    for (int off = 4; off; off >>= 1)
        mx = fmaxf(mx, __shfl_xor_sync(0xffffffffu, mx, off));

    // ---- pass B: exp, denominator, weighted gather-aggregate ----
    float den = 0.0f, a0 = 0.0f, a1 = 0.0f;
    for (int p0 = beg; p0 < end; p0 += 8) {
        int myp = p0 + sub;
        float c = 0.0f;
        int s = 0;
        if (myp < end) {
            c = __expf(d_alpha[(size_t)myp * 4 + h] - mx);
            s = d_csrc[myp];
        }
        int nb = end - p0;
        if (nb >= 8) {
#pragma unroll
            for (int j = 0; j < 8; j++) {
                float cj = __shfl_sync(0xffffffffu, c, h * 8 + j);
                int   sj = __shfl_sync(0xffffffffu, s, j);
                float2 v = *(const float2*)(d_xp + (size_t)sj * 64 + lane * 2);
                den += cj; a0 += cj * v.x; a1 += cj * v.y;
            }
        } else {
            for (int j = 0; j < nb; j++) {
                float cj = __shfl_sync(0xffffffffu, c, h * 8 + j);
                int   sj = __shfl_sync(0xffffffffu, s, j);
                float2 v = *(const float2*)(d_xp + (size_t)sj * 64 + lane * 2);
                den += cj; a0 += cj * v.x; a1 += cj * v.y;
            }
        }
    }
    float inv = 1.0f / (den + 1e-16f);
    float o0 = a0 * inv + b[lane * 2];
    float o1 = a1 * inv + b[lane * 2 + 1];
    if (dorelu) { o0 = fmaxf(o0, 0.0f); o1 = fmaxf(o1, 0.0f); }
    *(float2*)(out + (size_t)warp * 64 + lane * 2) = make_float2(o0, o1);
}

// ---------------- global mean pool ----------------
__global__ void k_pool(const int* __restrict__ batch, const float* __restrict__ h) {
    size_t t = (size_t)blockIdx.x * blockDim.x + threadIdx.x;
    int n = (int)(t >> 5);
    if (n >= NN) return;
    int c2 = (int)(t & 31) * 2;
    int g = batch[n];
    red2(&d_pool[g * 64 + c2], h[(size_t)n * 64 + c2], h[(size_t)n * 64 + c2 + 1]);
    if (c2 == 0) atomicAdd(&d_gcnt[g], 1.0f);
}

// ---------------- MLP head ----------------
__global__ void k_mlp(const float* __restrict__ fc1w, const float* __restrict__ fc1b,
                      const float* __restrict__ fc2w, const float* __restrict__ fc2b,
                      float* __restrict__ out) {
    int g = threadIdx.x;
    if (g >= NGRAPH) return;
    float ic = 1.0f / fmaxf(d_gcnt[g], 1.0f);
    float hr[64];
#pragma unroll
    for (int c = 0; c < 64; c++) hr[c] = d_pool[g * 64 + c] * ic;
    float y1[32];
#pragma unroll
    for (int j = 0; j < 32; j++) {
        float s = fc1b[j];
#pragma unroll
        for (int c = 0; c < 64; c++) s += hr[c] * fc1w[c * 32 + j];
        y1[j] = fmaxf(s, 0.0f);
    }
#pragma unroll
    for (int o = 0; o < 2; o++) {
        float s = fc2b[o];
#pragma unroll
        for (int j = 0; j < 32; j++) s += y1[j] * fc2w[j * 2 + o];
        out[g * 2 + o] = s;
    }
}

// ---------------- host ----------------
extern "C" void kernel_launch(void* const* d_in, const int* in_sizes, int n_in,
                              void* d_out, int out_size) {
    (void)in_sizes; (void)n_in; (void)out_size;
    const float* x    = (const float*)d_in[0];
    const int*   ei   = (const int*)d_in[1];
    const float* ea   = (const float*)d_in[2];
    const int*   batch= (const int*)d_in[3];
    const float* W0   = (const float*)d_in[4];
    const float* as0  = (const float*)d_in[5];
    const float* ad0  = (const float*)d_in[6];
    const float* We0  = (const float*)d_in[7];
    const float* ae0  = (const float*)d_in[8];
    const float* b0   = (const float*)d_in[9];
    const float* Wh   = (const float*)d_in[10];
    const float* ash  = (const float*)d_in[11];
    const float* adh  = (const float*)d_in[12];
    const float* Weh  = (const float*)d_in[13];
    const float* aeh  = (const float*)d_in[14];
    const float* bh   = (const float*)d_in[15];
    const float* fc1w = (const float*)d_in[16];
    const float* fc1b = (const float*)d_in[17];
    const float* fc2w = (const float*)d_in[18];
    const float* fc2b = (const float*)d_in[19];
    float* out = (float*)d_out;

    const int* src = ei;
    const int* dst = ei + NE;

    void *p_h0, *p_h1, *p_weatt;
    cudaGetSymbolAddress(&p_h0,   d_h0);
    cudaGetSymbolAddress(&p_h1,   d_h1);
    cudaGetSymbolAddress(&p_weatt,d_weatt);

    struct LayerCfg {
        const float* X; int fin; const float* W;
        const float* as; const float* ad; const float* b; float* hout; int relu;
    };
    LayerCfg L[3] = {
        { x,            32, W0,        as0,      ad0,      b0,      (float*)p_h0, 1 },
        { (float*)p_h0, 64, Wh,        ash,      adh,      bh,      (float*)p_h1, 0 },
        { (float*)p_h1, 64, Wh + 4096, ash + 64, adh + 64, bh + 64, (float*)p_h0, 0 },
    };

    // Launch order chosen so the 6th launch is k_agg (ncu -s 5 -c 1 capture target).
    // 1: project layer 0 (depends only on inputs)
    k_project<<<NN / 32, 256>>>(L[0].X, L[0].fin, L[0].W, L[0].as, L[0].ad);
    // 2: init (zeros cnt/mean/pool/gcnt + weatt for all layers)
    k_init<<<400, 256>>>(We0, ae0, Weh, aeh);
    // 3-5: CSR build
    k_count<<<(NE + 255) / 256, 256>>>(dst, ea);
    k_scan<<<1, 1024>>>();
    k_fill<<<(ESL + 255) / 256, 256>>>(src, dst, ea);
    // 6: k_agg layer 0  <-- profiled launch
    k_agg<<<(NN * 32 + 255) / 256, 256>>>((const float*)p_weatt + 0, L[0].b, L[0].relu, L[0].hout);

    for (int l = 1; l < 3; l++) {
        k_project<<<NN / 32, 256>>>(L[l].X, L[l].fin, L[l].W, L[l].as, L[l].ad);
        k_agg<<<(NN * 32 + 255) / 256, 256>>>((const float*)p_weatt + l * 32,
                                              L[l].b, L[l].relu, L[l].hout);
    }

    k_pool<<<(int)(((size_t)NN * 32 + 255) / 256), 256>>>(batch, (const float*)p_h0);
    k_mlp<<<1, 64>>>(fc1w, fc1b, fc2w, fc2b, out);
}

// round 6
// speedup vs baseline: 1.2706x; 1.2594x over previous
#include <cuda_runtime.h>
#include <math.h>

#define NN 100000
#define NE 1600000
#define ESL (NE + NN)
#define NGRAPH 64
#define NEG 0.2f
#define SCB 196          // ceil(NN / 512) scan blocks

// ---------------- scratch (device globals; no allocation) ----------------
__device__ float    d_cnt[NN];
__device__ float    d_mean[NN * 8];
__device__ float    d_xp[NN * 64];
__device__ float    d_als[NN * 4];
__device__ float    d_ald[NN * 4];
__device__ float    d_alpha[(size_t)ESL * 4];   // CSR order, coalesced
__device__ float    d_h0[NN * 64];
__device__ float    d_h1[NN * 64];
__device__ float    d_pool[NGRAPH * 64];
__device__ float    d_gcnt[NGRAPH];
__device__ float    d_weatt[3 * 32];            // all 3 layers precomputed
// CSR
__device__ int      d_roff[NN + 1];
__device__ int      d_cur[NN];
__device__ int      d_csrc[ESL];                // src node per CSR slot
__device__ float    d_ea_csr[(size_t)ESL * 8];  // edge attrs in CSR order
__device__ int      d_bsum[256];                // per-scan-block degree sums

// ---------------- helpers ----------------
__device__ __forceinline__ void red2(float* p, float a, float b) {
    asm volatile("red.global.add.v2.f32 [%0], {%1, %2};" :: "l"(p), "f"(a), "f"(b) : "memory");
}

// ---------------- self-loop mean edge-attr (sum) + in-degree count ----------------
__global__ void k_count(const int* __restrict__ dst, const float* __restrict__ ea) {
    int e = blockIdx.x * blockDim.x + threadIdx.x;
    if (e >= NE) return;
    int dd = dst[e];
    atomicAdd(&d_cnt[dd], 1.0f);
#pragma unroll
    for (int d = 0; d < 8; d += 2)
        red2(&d_mean[dd * 8 + d], ea[(size_t)e * 8 + d], ea[(size_t)e * 8 + d + 1]);
}

// ---------------- scan stage 1: per-block degree sums (512 nodes/block) ----------------
__global__ void k_s1() {
    __shared__ int sh[256];
    int t = threadIdx.x;
    int nb = blockIdx.x * 512 + t * 2;
    int s = 0;
    if (nb < NN) {      // NN even -> nb+1 < NN too
        float2 c = *(const float2*)&d_cnt[nb];
        s = (int)(c.x + 0.5f) + 1 + (int)(c.y + 0.5f) + 1;
    }
    sh[t] = s;
    __syncthreads();
#pragma unroll
    for (int off = 128; off; off >>= 1) {
        if (t < off) sh[t] += sh[t + off];
        __syncthreads();
    }
    if (t == 0) d_bsum[blockIdx.x] = sh[0];
}

// ---------------- scan stage 2: block base + local exclusive scan -> roff/cur ----------------
__global__ void k_s3() {
    __shared__ int sb[256];
    int t = threadIdx.x;
    sb[t] = (t < SCB) ? d_bsum[t] : 0;
    __syncthreads();
#pragma unroll
    for (int off = 1; off < 256; off <<= 1) {
        int v = (t >= off) ? sb[t - off] : 0;
        __syncthreads();
        sb[t] += v;
        __syncthreads();
    }
    int base = (blockIdx.x == 0) ? 0 : sb[blockIdx.x - 1];
    __syncthreads();

    int nb = blockIdx.x * 512 + t * 2;
    int d0 = 0, d1 = 0;
    if (nb < NN) {
        float2 c = *(const float2*)&d_cnt[nb];
        d0 = (int)(c.x + 0.5f) + 1;
        d1 = (int)(c.y + 0.5f) + 1;
    }
    sb[t] = d0 + d1;
    __syncthreads();
#pragma unroll
    for (int off = 1; off < 256; off <<= 1) {
        int v = (t >= off) ? sb[t - off] : 0;
        __syncthreads();
        sb[t] += v;
        __syncthreads();
    }
    int off0 = base + sb[t] - (d0 + d1);   // exclusive
    if (nb < NN) {
        d_roff[nb] = off0;     d_cur[nb] = off0;
        d_roff[nb + 1] = off0 + d0; d_cur[nb + 1] = off0 + d0;
    }
}

// ---------------- CSR fill: src ids + permuted edge attrs (self-loop rows get mean) ----------------
__global__ void k_fill(const int* __restrict__ src, const int* __restrict__ dst,
                       const float* __restrict__ ea) {
    int e = blockIdx.x * blockDim.x + threadIdx.x;
    if (e >= ESL) return;
    int s, dd;
    float4 a0, a1;
    if (e < NE) {
        s = src[e]; dd = dst[e];
        const float4* a = (const float4*)(ea + (size_t)e * 8);
        a0 = a[0]; a1 = a[1];
    } else {
        s = dd = e - NE;
        const float4* a = (const float4*)(d_mean + (size_t)(e - NE) * 8);
        a0 = a[0]; a1 = a[1];
        float ic = 1.0f / fmaxf(d_cnt[dd], 1.0f);
        a0.x *= ic; a0.y *= ic; a0.z *= ic; a0.w *= ic;
        a1.x *= ic; a1.y *= ic; a1.z *= ic; a1.w *= ic;
    }
    int pos = atomicAdd(&d_cur[dd], 1);
    d_csrc[pos] = s;
    float4* o = (float4*)(d_ea_csr + (size_t)pos * 8);
    o[0] = a0; o[1] = a1;
}

// ---------------- projection (R3 grid-strided form) + optional init prologue ----------------
__global__ void k_project(const float* __restrict__ X, int fin, const float* __restrict__ W,
                          const float* __restrict__ as_, const float* __restrict__ ad_,
                          int doinit,
                          const float* __restrict__ We0, const float* __restrict__ ae0,
                          const float* __restrict__ Weh, const float* __restrict__ aeh) {
    __shared__ float sW[64 * 64];
    __shared__ float sx[4 * 64];
    __shared__ float sa[64], sd[64];
    int tid = threadIdx.x;
    if (doinit) {
        int gt = blockIdx.x * 256 + tid, gs = gridDim.x * 256;
        for (int i = gt; i < NN * 8; i += gs) d_mean[i] = 0.0f;
        for (int i = gt; i < NN; i += gs) d_cnt[i] = 0.0f;
        for (int i = gt; i < NGRAPH * 64; i += gs) d_pool[i] = 0.0f;
        for (int i = gt; i < NGRAPH; i += gs) d_gcnt[i] = 0.0f;
        if (gt < 96) {
            int l = gt >> 5, r = gt & 31;
            int d = r >> 2, h = r & 3;
            const float* We = (l == 0) ? We0 : (Weh + (l - 1) * 512);
            const float* ae = (l == 0) ? ae0 : (aeh + (l - 1) * 64);
            float s = 0.0f;
#pragma unroll
            for (int c = 0; c < 16; c++) s += We[d * 64 + h * 16 + c] * ae[h * 16 + c];
            d_weatt[l * 32 + d * 4 + h] = s;
        }
        if (gt == 0) d_roff[NN] = ESL;
    }
    for (int i = tid; i < fin * 64; i += 256) sW[i] = W[i];
    if (tid < 64) { sa[tid] = as_[tid]; sd[tid] = ad_[tid]; }
    __syncthreads();
    int slot = tid >> 6, col = tid & 63;
    for (int base = blockIdx.x * 4; base < NN; base += gridDim.x * 4) {
        int n = base + slot;
        if (n < NN && col < fin) sx[slot * 64 + col] = X[(size_t)n * fin + col];
        __syncthreads();
        if (n < NN) {
            float acc = 0.0f;
#pragma unroll 4
            for (int i = 0; i < fin; i += 4) {
                float4 xv = *(const float4*)(sx + slot * 64 + i);
                acc += xv.x * sW[(i + 0) * 64 + col];
                acc += xv.y * sW[(i + 1) * 64 + col];
                acc += xv.z * sW[(i + 2) * 64 + col];
                acc += xv.w * sW[(i + 3) * 64 + col];
            }
            d_xp[(size_t)n * 64 + col] = acc;
            float ps = acc * sa[col], pd = acc * sd[col];
#pragma unroll
            for (int off = 8; off; off >>= 1) {
                ps += __shfl_xor_sync(0xffffffffu, ps, off);
                pd += __shfl_xor_sync(0xffffffffu, pd, off);
            }
            if ((col & 15) == 0) {
                int h = col >> 4;
                d_als[n * 4 + h] = ps;
                d_ald[n * 4 + h] = pd;
            }
        }
        __syncthreads();
    }
}

// ---------------- fused two-pass softmax + aggregate + bias: warp per dst node ----------------
__global__ void k_agg(const float* __restrict__ weatt, const float* __restrict__ b,
                      int dorelu, float* __restrict__ out) {
    __shared__ float sw[32];
    int tid = threadIdx.x;
    if (tid < 32) sw[tid] = weatt[tid];
    __syncthreads();
    int warp = (blockIdx.x * blockDim.x + tid) >> 5;
    if (warp >= NN) return;
    int lane = tid & 31;
    int h = lane >> 3, sub = lane & 7;
    int beg = d_roff[warp];
    int end = d_roff[warp + 1];
    float ald_h = d_ald[warp * 4 + h];
    float wd[8];
#pragma unroll
    for (int d = 0; d < 8; d++) wd[d] = sw[d * 4 + h];

    // ---- pass A: alpha per (edge, head), running max in registers ----
    float mx = -INFINITY;
    for (int p0 = beg; p0 < end; p0 += 8) {
        int myp = p0 + sub;
        float al = -INFINITY;
        if (myp < end) {
            int s = d_csrc[myp];
            const float4* ap = (const float4*)(d_ea_csr + (size_t)myp * 8);
            float4 e0 = ap[0], e1 = ap[1];
            float ale = e0.x * wd[0] + e0.y * wd[1] + e0.z * wd[2] + e0.w * wd[3]
                      + e1.x * wd[4] + e1.y * wd[5] + e1.z * wd[6] + e1.w * wd[7];
            float a = d_als[s * 4 + h] + ald_h + ale;
            al = a > 0.0f ? a : NEG * a;
            d_alpha[(size_t)myp * 4 + h] = al;   // coalesced 128B per warp batch
        }
        mx = fmaxf(mx, al);
    }
#pragma unroll
    for (int off = 4; off; off >>= 1)
        mx = fmaxf(mx, __shfl_xor_sync(0xffffffffu, mx, off));

    // ---- pass B: exp, denominator, weighted gather-aggregate ----
    float den = 0.0f, a0 = 0.0f, a1 = 0.0f;
    for (int p0 = beg; p0 < end; p0 += 8) {
        int myp = p0 + sub;
        float c = 0.0f;
        int s = 0;
        if (myp < end) {
            c = __expf(d_alpha[(size_t)myp * 4 + h] - mx);
            s = d_csrc[myp];
        }
        int nb = end - p0;
        if (nb >= 8) {
#pragma unroll
            for (int j = 0; j < 8; j++) {
                float cj = __shfl_sync(0xffffffffu, c, h * 8 + j);
                int   sj = __shfl_sync(0xffffffffu, s, j);
                float2 v = *(const float2*)(d_xp + (size_t)sj * 64 + lane * 2);
                den += cj; a0 += cj * v.x; a1 += cj * v.y;
            }
        } else {
            for (int j = 0; j < nb; j++) {
                float cj = __shfl_sync(0xffffffffu, c, h * 8 + j);
                int   sj = __shfl_sync(0xffffffffu, s, j);
                float2 v = *(const float2*)(d_xp + (size_t)sj * 64 + lane * 2);
                den += cj; a0 += cj * v.x; a1 += cj * v.y;
            }
        }
    }
    float inv = 1.0f / (den + 1e-16f);
    float o0 = a0 * inv + b[lane * 2];
    float o1 = a1 * inv + b[lane * 2 + 1];
    if (dorelu) { o0 = fmaxf(o0, 0.0f); o1 = fmaxf(o1, 0.0f); }
    *(float2*)(out + (size_t)warp * 64 + lane * 2) = make_float2(o0, o1);
}

// ---------------- global mean pool ----------------
__global__ void k_pool(const int* __restrict__ batch, const float* __restrict__ h) {
    size_t t = (size_t)blockIdx.x * blockDim.x + threadIdx.x;
    int n = (int)(t >> 5);
    if (n >= NN) return;
    int c2 = (int)(t & 31) * 2;
    int g = batch[n];
    red2(&d_pool[g * 64 + c2], h[(size_t)n * 64 + c2], h[(size_t)n * 64 + c2 + 1]);
    if (c2 == 0) atomicAdd(&d_gcnt[g], 1.0f);
}

// ---------------- MLP head ----------------
__global__ void k_mlp(const float* __restrict__ fc1w, const float* __restrict__ fc1b,
                      const float* __restrict__ fc2w, const float* __restrict__ fc2b,
                      float* __restrict__ out) {
    int g = threadIdx.x;
    if (g >= NGRAPH) return;
    float ic = 1.0f / fmaxf(d_gcnt[g], 1.0f);
    float hr[64];
#pragma unroll
    for (int c = 0; c < 64; c++) hr[c] = d_pool[g * 64 + c] * ic;
    float y1[32];
#pragma unroll
    for (int j = 0; j < 32; j++) {
        float s = fc1b[j];
#pragma unroll
        for (int c = 0; c < 64; c++) s += hr[c] * fc1w[c * 32 + j];
        y1[j] = fmaxf(s, 0.0f);
    }
#pragma unroll
    for (int o = 0; o < 2; o++) {
        float s = fc2b[o];
#pragma unroll
        for (int j = 0; j < 32; j++) s += y1[j] * fc2w[j * 2 + o];
        out[g * 2 + o] = s;
    }
}

// ---------------- host ----------------
extern "C" void kernel_launch(void* const* d_in, const int* in_sizes, int n_in,
                              void* d_out, int out_size) {
    (void)in_sizes; (void)n_in; (void)out_size;
    const float* x    = (const float*)d_in[0];
    const int*   ei   = (const int*)d_in[1];
    const float* ea   = (const float*)d_in[2];
    const int*   batch= (const int*)d_in[3];
    const float* W0   = (const float*)d_in[4];
    const float* as0  = (const float*)d_in[5];
    const float* ad0  = (const float*)d_in[6];
    const float* We0  = (const float*)d_in[7];
    const float* ae0  = (const float*)d_in[8];
    const float* b0   = (const float*)d_in[9];
    const float* Wh   = (const float*)d_in[10];
    const float* ash  = (const float*)d_in[11];
    const float* adh  = (const float*)d_in[12];
    const float* Weh  = (const float*)d_in[13];
    const float* aeh  = (const float*)d_in[14];
    const float* bh   = (const float*)d_in[15];
    const float* fc1w = (const float*)d_in[16];
    const float* fc1b = (const float*)d_in[17];
    const float* fc2w = (const float*)d_in[18];
    const float* fc2b = (const float*)d_in[19];
    float* out = (float*)d_out;

    const int* src = ei;
    const int* dst = ei + NE;

    void *p_h0, *p_h1, *p_weatt;
    cudaGetSymbolAddress(&p_h0,   d_h0);
    cudaGetSymbolAddress(&p_h1,   d_h1);
    cudaGetSymbolAddress(&p_weatt,d_weatt);

    struct LayerCfg {
        const float* X; int fin; const float* W;
        const float* as; const float* ad; const float* b; float* hout; int relu;
    };
    LayerCfg L[3] = {
        { x,            32, W0,        as0,      ad0,      b0,      (float*)p_h0, 1 },
        { (float*)p_h0, 64, Wh,        ash,      adh,      bh,      (float*)p_h1, 0 },
        { (float*)p_h1, 64, Wh + 4096, ash + 64, adh + 64, bh + 64, (float*)p_h0, 0 },
    };

    // Launch order: 6th launch is k_agg layer 0 (ncu -s 5 -c 1 capture target).
    // 1: project layer 0 + init prologue
    k_project<<<1184, 256>>>(L[0].X, L[0].fin, L[0].W, L[0].as, L[0].ad,
                             1, We0, ae0, Weh, aeh);
    // 2-5: CSR build
    k_count<<<(NE + 255) / 256, 256>>>(dst, ea);
    k_s1<<<SCB, 256>>>();
    k_s3<<<SCB, 256>>>();
    k_fill<<<(ESL + 255) / 256, 256>>>(src, dst, ea);
    // 6: k_agg layer 0  <-- profiled launch
    k_agg<<<(NN * 32 + 255) / 256, 256>>>((const float*)p_weatt + 0, L[0].b, L[0].relu, L[0].hout);

    for (int l = 1; l < 3; l++) {
        k_project<<<1184, 256>>>(L[l].X, L[l].fin, L[l].W, L[l].as, L[l].ad,
                                 0, We0, ae0, Weh, aeh);
        k_agg<<<(NN * 32 + 255) / 256, 256>>>((const float*)p_weatt + l * 32,
                                              L[l].b, L[l].relu, L[l].hout);
    }

    k_pool<<<(int)(((size_t)NN * 32 + 255) / 256), 256>>>(batch, (const float*)p_h0);
    k_mlp<<<1, 64>>>(fc1w, fc1b, fc2w, fc2b, out);
}

// round 7
// speedup vs baseline: 1.2878x; 1.0135x over previous
#include <cuda_runtime.h>
#include <math.h>

#define NN 100000
#define NE 1600000
#define ESL (NE + NN)
#define NGRAPH 64
#define NEG 0.2f
#define SCB 196          // ceil(NN / 512) scan blocks
#define PB  1184         // project blocks inside fused fillproj

// ---------------- scratch (device globals; no allocation) ----------------
__device__ float    d_cnt[NN];
__device__ float    d_mean[NN * 8];
__device__ float    d_xp[NN * 64];
__device__ float    d_als[NN * 4];
__device__ float    d_ald[NN * 4];
__device__ float    d_h0[NN * 64];
__device__ float    d_h1[NN * 64];
__device__ float    d_pool[NGRAPH * 64];
__device__ float    d_gcnt[NGRAPH];
__device__ float    d_weatt[3 * 32];
// CSR
__device__ int      d_roff[NN + 1];
__device__ int      d_cur[NN];
__device__ int      d_csrc[ESL];
__device__ float    d_ea_csr[(size_t)ESL * 8];
__device__ int      d_flagsum[SCB];             // lookback: 0 = not ready, else localsum+1

// ---------------- helpers ----------------
__device__ __forceinline__ void red2(float* p, float a, float b) {
    asm volatile("red.global.add.v2.f32 [%0], {%1, %2};" :: "l"(p), "f"(a), "f"(b) : "memory");
}

// ---------------- self-loop mean edge-attr (sum) + in-degree count ----------------
__global__ void k_count(const int* __restrict__ dst, const float* __restrict__ ea) {
    int e = blockIdx.x * blockDim.x + threadIdx.x;
    if (e >= NE) return;
    int dd = dst[e];
    atomicAdd(&d_cnt[dd], 1.0f);
#pragma unroll
    for (int d = 0; d < 8; d += 2)
        red2(&d_mean[dd * 8 + d], ea[(size_t)e * 8 + d], ea[(size_t)e * 8 + d + 1]);
}

// ---------------- one-kernel scan (decoupled lookback) + weatt + roff[NN] ----------------
__global__ void k_scan(const float* __restrict__ We0, const float* __restrict__ ae0,
                       const float* __restrict__ Weh, const float* __restrict__ aeh) {
    __shared__ int sh[256];
    __shared__ int sp[256];
    int t = threadIdx.x, bid = blockIdx.x;
    int nb = bid * 512 + t * 2;
    int d0 = 0, d1 = 0;
    if (nb < NN) {                      // NN even -> nb+1 < NN too
        float2 c = *(const float2*)&d_cnt[nb];
        d0 = (int)(c.x + 0.5f) + 1;
        d1 = (int)(c.y + 0.5f) + 1;
    }
    sh[t] = d0 + d1;
    __syncthreads();
    // inclusive scan over 256
#pragma unroll
    for (int off = 1; off < 256; off <<= 1) {
        int v = (t >= off) ? sh[t - off] : 0;
        __syncthreads();
        sh[t] += v;
        __syncthreads();
    }
    int total = sh[255];
    if (t == 0) {
        __threadfence();
        atomicExch(&d_flagsum[bid], total + 1);
    }
    // lookback: thread t (< bid) spins on predecessor t
    int pre = 0;
    if (t < bid) {
        volatile int* f = &d_flagsum[t];
        int x;
        while ((x = *f) == 0) { }
        pre = x - 1;
    }
    sp[t] = pre;
    __syncthreads();
#pragma unroll
    for (int off = 128; off; off >>= 1) {
        if (t < off) sp[t] += sp[t + off];
        __syncthreads();
    }
    int base = sp[0];
    int off0 = base + sh[t] - (d0 + d1);   // exclusive prefix for this thread's node pair
    if (nb < NN) {
        d_roff[nb] = off0;          d_cur[nb] = off0;
        d_roff[nb + 1] = off0 + d0; d_cur[nb + 1] = off0 + d0;
    }
    if (bid == 0) {
        if (t < 96) {
            int l = t >> 5, r = t & 31;
            int d = r >> 2, h = r & 3;
            const float* We = (l == 0) ? We0 : (Weh + (l - 1) * 512);
            const float* ae = (l == 0) ? ae0 : (aeh + (l - 1) * 64);
            float s = 0.0f;
#pragma unroll
            for (int c = 0; c < 16; c++) s += We[d * 64 + h * 16 + c] * ae[h * 16 + c];
            d_weatt[l * 32 + d * 4 + h] = s;
        }
        if (t == 0) d_roff[NN] = ESL;
    }
}

// ---------------- projection body: xp = X @ W ; al_s/al_d per (node, head) ----------------
__device__ __forceinline__ void project_body(
        int bid, int nblocks,
        const float* __restrict__ X, int fin, const float* __restrict__ W,
        const float* __restrict__ as_, const float* __restrict__ ad_,
        float* sW, float* sx, float* sa, float* sd) {
    int tid = threadIdx.x;
    for (int i = tid; i < fin * 64; i += 256) sW[i] = W[i];
    if (tid < 64) { sa[tid] = as_[tid]; sd[tid] = ad_[tid]; }
    __syncthreads();
    int slot = tid >> 6, col = tid & 63;
    for (int base = bid * 4; base < NN; base += nblocks * 4) {
        int n = base + slot;
        if (n < NN && col < fin) sx[slot * 64 + col] = X[(size_t)n * fin + col];
        __syncthreads();
        if (n < NN) {
            float acc = 0.0f;
#pragma unroll 4
            for (int i = 0; i < fin; i += 4) {
                float4 xv = *(const float4*)(sx + slot * 64 + i);
                acc += xv.x * sW[(i + 0) * 64 + col];
                acc += xv.y * sW[(i + 1) * 64 + col];
                acc += xv.z * sW[(i + 2) * 64 + col];
                acc += xv.w * sW[(i + 3) * 64 + col];
            }
            d_xp[(size_t)n * 64 + col] = acc;
            float ps = acc * sa[col], pd = acc * sd[col];
#pragma unroll
            for (int off = 8; off; off >>= 1) {
                ps += __shfl_xor_sync(0xffffffffu, ps, off);
                pd += __shfl_xor_sync(0xffffffffu, pd, off);
            }
            if ((col & 15) == 0) {
                int h = col >> 4;
                d_als[n * 4 + h] = ps;
                d_ald[n * 4 + h] = pd;
            }
        }
        __syncthreads();
    }
}

// ---------------- fused: CSR fill (blocks >= PB) + project layer0 (blocks < PB) ----------------
__global__ void k_fillproj(const int* __restrict__ src, const int* __restrict__ dst,
                           const float* __restrict__ ea,
                           const float* __restrict__ X, int fin, const float* __restrict__ W,
                           const float* __restrict__ as_, const float* __restrict__ ad_) {
    __shared__ float sW[64 * 64];
    __shared__ float sx[4 * 64];
    __shared__ float sa[64], sd[64];
    if (blockIdx.x < PB) {
        project_body(blockIdx.x, PB, X, fin, W, as_, ad_, sW, sx, sa, sd);
        return;
    }
    int e = (blockIdx.x - PB) * 256 + threadIdx.x;
    if (e >= ESL) return;
    int s, dd;
    float4 a0, a1;
    if (e < NE) {
        s = src[e]; dd = dst[e];
        const float4* a = (const float4*)(ea + (size_t)e * 8);
        a0 = a[0]; a1 = a[1];
    } else {
        s = dd = e - NE;
        const float4* a = (const float4*)(d_mean + (size_t)(e - NE) * 8);
        a0 = a[0]; a1 = a[1];
        float ic = 1.0f / fmaxf(d_cnt[dd], 1.0f);
        a0.x *= ic; a0.y *= ic; a0.z *= ic; a0.w *= ic;
        a1.x *= ic; a1.y *= ic; a1.z *= ic; a1.w *= ic;
    }
    int pos = atomicAdd(&d_cur[dd], 1);
    d_csrc[pos] = s;
    float4* o = (float4*)(d_ea_csr + (size_t)pos * 8);
    o[0] = a0; o[1] = a1;
}

// ---------------- standalone projection (layers 1,2) ----------------
__global__ void k_project(const float* __restrict__ X, int fin, const float* __restrict__ W,
                          const float* __restrict__ as_, const float* __restrict__ ad_) {
    __shared__ float sW[64 * 64];
    __shared__ float sx[4 * 64];
    __shared__ float sa[64], sd[64];
    project_body(blockIdx.x, gridDim.x, X, fin, W, as_, ad_, sW, sx, sa, sd);
}

// ---------------- fused single-pass: logits + exp + softmax-aggregate + bias
// (no max subtraction: alpha is O(+-20), exp cannot overflow; softmax shift-invariant)
__global__ void k_agg(const float* __restrict__ weatt, const float* __restrict__ b,
                      int dorelu, float* __restrict__ out) {
    __shared__ float sw[32];
    int tid = threadIdx.x;
    if (tid < 32) sw[tid] = weatt[tid];
    __syncthreads();
    int warp = (blockIdx.x * blockDim.x + tid) >> 5;
    if (warp >= NN) return;
    int lane = tid & 31;
    int h = lane >> 3, sub = lane & 7;
    int beg = d_roff[warp];
    int end = d_roff[warp + 1];
    float ald_h = d_ald[warp * 4 + h];
    float wd[8];
#pragma unroll
    for (int d = 0; d < 8; d++) wd[d] = sw[d * 4 + h];

    float den = 0.0f, a0 = 0.0f, a1 = 0.0f;
    for (int p0 = beg; p0 < end; p0 += 8) {
        int myp = p0 + sub;
        float c = 0.0f;
        int s = 0;
        if (myp < end) {
            s = d_csrc[myp];
            const float4* ap = (const float4*)(d_ea_csr + (size_t)myp * 8);
            float4 e0 = ap[0], e1 = ap[1];
            float ale = e0.x * wd[0] + e0.y * wd[1] + e0.z * wd[2] + e0.w * wd[3]
                      + e1.x * wd[4] + e1.y * wd[5] + e1.z * wd[6] + e1.w * wd[7];
            float a = d_als[s * 4 + h] + ald_h + ale;
            float al = a > 0.0f ? a : NEG * a;
            c = __expf(al);
        }
        int nb = end - p0;
        if (nb >= 8) {
#pragma unroll
            for (int j = 0; j < 8; j++) {
                float cj = __shfl_sync(0xffffffffu, c, h * 8 + j);
                int   sj = __shfl_sync(0xffffffffu, s, j);
                float2 v = *(const float2*)(d_xp + (size_t)sj * 64 + lane * 2);
                den += cj; a0 += cj * v.x; a1 += cj * v.y;
            }
        } else {
            for (int j = 0; j < nb; j++) {
                float cj = __shfl_sync(0xffffffffu, c, h * 8 + j);
                int   sj = __shfl_sync(0xffffffffu, s, j);
                float2 v = *(const float2*)(d_xp + (size_t)sj * 64 + lane * 2);
                den += cj; a0 += cj * v.x; a1 += cj * v.y;
            }
        }
    }
    float inv = 1.0f / (den + 1e-16f);
    float o0 = a0 * inv + b[lane * 2];
    float o1 = a1 * inv + b[lane * 2 + 1];
    if (dorelu) { o0 = fmaxf(o0, 0.0f); o1 = fmaxf(o1, 0.0f); }
    *(float2*)(out + (size_t)warp * 64 + lane * 2) = make_float2(o0, o1);
}

// ---------------- global mean pool ----------------
__global__ void k_pool(const int* __restrict__ batch, const float* __restrict__ h) {
    size_t t = (size_t)blockIdx.x * blockDim.x + threadIdx.x;
    int n = (int)(t >> 5);
    if (n >= NN) return;
    int c2 = (int)(t & 31) * 2;
    int g = batch[n];
    red2(&d_pool[g * 64 + c2], h[(size_t)n * 64 + c2], h[(size_t)n * 64 + c2 + 1]);
    if (c2 == 0) atomicAdd(&d_gcnt[g], 1.0f);
}

// ---------------- MLP head ----------------
__global__ void k_mlp(const float* __restrict__ fc1w, const float* __restrict__ fc1b,
                      const float* __restrict__ fc2w, const float* __restrict__ fc2b,
                      float* __restrict__ out) {
    int g = threadIdx.x;
    if (g >= NGRAPH) return;
    float ic = 1.0f / fmaxf(d_gcnt[g], 1.0f);
    float hr[64];
#pragma unroll
    for (int c = 0; c < 64; c++) hr[c] = d_pool[g * 64 + c] * ic;
    float y1[32];
#pragma unroll
    for (int j = 0; j < 32; j++) {
        float s = fc1b[j];
#pragma unroll
        for (int c = 0; c < 64; c++) s += hr[c] * fc1w[c * 32 + j];
        y1[j] = fmaxf(s, 0.0f);
    }
#pragma unroll
    for (int o = 0; o < 2; o++) {
        float s = fc2b[o];
#pragma unroll
        for (int j = 0; j < 32; j++) s += y1[j] * fc2w[j * 2 + o];
        out[g * 2 + o] = s;
    }
}

// ---------------- host ----------------
extern "C" void kernel_launch(void* const* d_in, const int* in_sizes, int n_in,
                              void* d_out, int out_size) {
    (void)in_sizes; (void)n_in; (void)out_size;
    const float* x    = (const float*)d_in[0];
    const int*   ei   = (const int*)d_in[1];
    const float* ea   = (const float*)d_in[2];
    const int*   batch= (const int*)d_in[3];
    const float* W0   = (const float*)d_in[4];
    const float* as0  = (const float*)d_in[5];
    const float* ad0  = (const float*)d_in[6];
    const float* We0  = (const float*)d_in[7];
    const float* ae0  = (const float*)d_in[8];
    const float* b0   = (const float*)d_in[9];
    const float* Wh   = (const float*)d_in[10];
    const float* ash  = (const float*)d_in[11];
    const float* adh  = (const float*)d_in[12];
    const float* Weh  = (const float*)d_in[13];
    const float* aeh  = (const float*)d_in[14];
    const float* bh   = (const float*)d_in[15];
    const float* fc1w = (const float*)d_in[16];
    const float* fc1b = (const float*)d_in[17];
    const float* fc2w = (const float*)d_in[18];
    const float* fc2b = (const float*)d_in[19];
    float* out = (float*)d_out;

    const int* src = ei;
    const int* dst = ei + NE;

    void *p_cnt, *p_mean, *p_pool, *p_gcnt, *p_flag, *p_h0, *p_h1, *p_weatt;
    cudaGetSymbolAddress(&p_cnt,  d_cnt);
    cudaGetSymbolAddress(&p_mean, d_mean);
    cudaGetSymbolAddress(&p_pool, d_pool);
    cudaGetSymbolAddress(&p_gcnt, d_gcnt);
    cudaGetSymbolAddress(&p_flag, d_flagsum);
    cudaGetSymbolAddress(&p_h0,   d_h0);
    cudaGetSymbolAddress(&p_h1,   d_h1);
    cudaGetSymbolAddress(&p_weatt,d_weatt);

    struct LayerCfg {
        const float* X; int fin; const float* W;
        const float* as; const float* ad; const float* b; float* hout; int relu;
    };
    LayerCfg L[3] = {
        { x,            32, W0,        as0,      ad0,      b0,      (float*)p_h0, 1 },
        { (float*)p_h0, 64, Wh,        ash,      adh,      bh,      (float*)p_h1, 0 },
        { (float*)p_h1, 64, Wh + 4096, ash + 64, adh + 64, bh + 64, (float*)p_h0, 0 },
    };

    // zero scratch (async memsets do not count as kernel launches for ncu skip)
    cudaMemsetAsync(p_cnt,  0, NN * sizeof(float));
    cudaMemsetAsync(p_mean, 0, NN * 8 * sizeof(float));
    cudaMemsetAsync(p_flag, 0, SCB * sizeof(int));
    cudaMemsetAsync(p_pool, 0, NGRAPH * 64 * sizeof(float));
    cudaMemsetAsync(p_gcnt, 0, NGRAPH * sizeof(float));

    // kernel launches: #4 is k_agg layer 0 (ncu capture target)
    k_count<<<(NE + 255) / 256, 256>>>(dst, ea);                                  // 1
    k_scan<<<SCB, 256>>>(We0, ae0, Weh, aeh);                                     // 2
    k_fillproj<<<PB + (ESL + 255) / 256, 256>>>(src, dst, ea,                     // 3
                                                L[0].X, L[0].fin, L[0].W, L[0].as, L[0].ad);
    k_agg<<<(NN * 32 + 255) / 256, 256>>>((const float*)p_weatt + 0,              // 4 <-- profiled
                                          L[0].b, L[0].relu, L[0].hout);
    for (int l = 1; l < 3; l++) {
        k_project<<<1184, 256>>>(L[l].X, L[l].fin, L[l].W, L[l].as, L[l].ad);
        k_agg<<<(NN * 32 + 255) / 256, 256>>>((const float*)p_weatt + l * 32,
                                              L[l].b, L[l].relu, L[l].hout);
    }

    k_pool<<<(int)(((size_t)NN * 32 + 255) / 256), 256>>>(batch, (const float*)p_h0);
    k_mlp<<<1, 64>>>(fc1w, fc1b, fc2w, fc2b, out);
}

// round 8
// speedup vs baseline: 1.2897x; 1.0015x over previous
#include <cuda_runtime.h>
#include <math.h>

#define NN 100000
#define NE 1600000
#define ESL (NE + NN)
#define NGRAPH 64
#define NEG 0.2f
#define SCB 196          // ceil(NN / 512) scan blocks
#define PB  1184         // project blocks inside fused fillproj

// ---------------- scratch (device globals; no allocation) ----------------
__device__ float    d_cnt[NN];
__device__ float    d_mean[NN * 8];
__device__ float    d_xp[NN * 64];
__device__ float    d_als[NN * 4];
__device__ float    d_ald[NN * 4];
__device__ float    d_h0[NN * 64];
__device__ float    d_h1[NN * 64];
__device__ float    d_pool[NGRAPH * 64];
__device__ float    d_gcnt[NGRAPH];
__device__ float    d_weatt[3 * 32];
// CSR
__device__ int      d_roff[NN + 1];
__device__ int      d_cur[NN];
__device__ int      d_csrc[ESL];
__device__ float    d_ale[3][(size_t)ESL * 4];  // per-layer edge logit contribution
__device__ int      d_flagsum[SCB];             // lookback: 0 = not ready, else localsum+1

// ---------------- helpers ----------------
__device__ __forceinline__ void red2(float* p, float a, float b) {
    asm volatile("red.global.add.v2.f32 [%0], {%1, %2};" :: "l"(p), "f"(a), "f"(b) : "memory");
}

// ---------------- self-loop mean edge-attr (sum) + in-degree count ----------------
__global__ void k_count(const int* __restrict__ dst, const float* __restrict__ ea) {
    int e = blockIdx.x * blockDim.x + threadIdx.x;
    if (e >= NE) return;
    int dd = dst[e];
    atomicAdd(&d_cnt[dd], 1.0f);
#pragma unroll
    for (int d = 0; d < 8; d += 2)
        red2(&d_mean[dd * 8 + d], ea[(size_t)e * 8 + d], ea[(size_t)e * 8 + d + 1]);
}

// ---------------- one-kernel scan (decoupled lookback) + weatt + roff[NN] ----------------
__global__ void k_scan(const float* __restrict__ We0, const float* __restrict__ ae0,
                       const float* __restrict__ Weh, const float* __restrict__ aeh) {
    __shared__ int sh[256];
    __shared__ int sp[256];
    int t = threadIdx.x, bid = blockIdx.x;
    int nb = bid * 512 + t * 2;
    int d0 = 0, d1 = 0;
    if (nb < NN) {                      // NN even -> nb+1 < NN too
        float2 c = *(const float2*)&d_cnt[nb];
        d0 = (int)(c.x + 0.5f) + 1;
        d1 = (int)(c.y + 0.5f) + 1;
    }
    sh[t] = d0 + d1;
    __syncthreads();
#pragma unroll
    for (int off = 1; off < 256; off <<= 1) {
        int v = (t >= off) ? sh[t - off] : 0;
        __syncthreads();
        sh[t] += v;
        __syncthreads();
    }
    int total = sh[255];
    if (t == 0) {
        __threadfence();
        atomicExch(&d_flagsum[bid], total + 1);
    }
    int pre = 0;
    if (t < bid) {
        volatile int* f = &d_flagsum[t];
        int x;
        while ((x = *f) == 0) { }
        pre = x - 1;
    }
    sp[t] = pre;
    __syncthreads();
#pragma unroll
    for (int off = 128; off; off >>= 1) {
        if (t < off) sp[t] += sp[t + off];
        __syncthreads();
    }
    int base = sp[0];
    int off0 = base + sh[t] - (d0 + d1);
    if (nb < NN) {
        d_roff[nb] = off0;          d_cur[nb] = off0;
        d_roff[nb + 1] = off0 + d0; d_cur[nb + 1] = off0 + d0;
    }
    if (bid == 0) {
        if (t < 96) {
            int l = t >> 5, r = t & 31;
            int d = r >> 2, h = r & 3;
            const float* We = (l == 0) ? We0 : (Weh + (l - 1) * 512);
            const float* ae = (l == 0) ? ae0 : (aeh + (l - 1) * 64);
            float s = 0.0f;
#pragma unroll
            for (int c = 0; c < 16; c++) s += We[d * 64 + h * 16 + c] * ae[h * 16 + c];
            d_weatt[l * 32 + d * 4 + h] = s;
        }
        if (t == 0) d_roff[NN] = ESL;
    }
}

// ---------------- projection body: xp = X @ W ; al_s/al_d per (node, head) ----------------
__device__ __forceinline__ void project_body(
        int bid, int nblocks,
        const float* __restrict__ X, int fin, const float* __restrict__ W,
        const float* __restrict__ as_, const float* __restrict__ ad_,
        float* sW, float* sx, float* sa, float* sd) {
    int tid = threadIdx.x;
    for (int i = tid; i < fin * 64; i += 256) sW[i] = W[i];
    if (tid < 64) { sa[tid] = as_[tid]; sd[tid] = ad_[tid]; }
    __syncthreads();
    int slot = tid >> 6, col = tid & 63;
    for (int base = bid * 4; base < NN; base += nblocks * 4) {
        int n = base + slot;
        if (n < NN && col < fin) sx[slot * 64 + col] = X[(size_t)n * fin + col];
        __syncthreads();
        if (n < NN) {
            float acc = 0.0f;
#pragma unroll 4
            for (int i = 0; i < fin; i += 4) {
                float4 xv = *(const float4*)(sx + slot * 64 + i);
                acc += xv.x * sW[(i + 0) * 64 + col];
                acc += xv.y * sW[(i + 1) * 64 + col];
                acc += xv.z * sW[(i + 2) * 64 + col];
                acc += xv.w * sW[(i + 3) * 64 + col];
            }
            d_xp[(size_t)n * 64 + col] = acc;
            float ps = acc * sa[col], pd = acc * sd[col];
#pragma unroll
            for (int off = 8; off; off >>= 1) {
                ps += __shfl_xor_sync(0xffffffffu, ps, off);
                pd += __shfl_xor_sync(0xffffffffu, pd, off);
            }
            if ((col & 15) == 0) {
                int h = col >> 4;
                d_als[n * 4 + h] = ps;
                d_ald[n * 4 + h] = pd;
            }
        }
        __syncthreads();
    }
}

// ---------------- fill body: CSR src + per-layer precomputed edge logits ----------------
__device__ __forceinline__ void fill_body(int e, const int* __restrict__ src,
                                          const int* __restrict__ dst,
                                          const float* __restrict__ ea,
                                          const float* sw) {
    int s, dd;
    float a[8];
    if (e < NE) {
        s = src[e]; dd = dst[e];
        const float4* ap = (const float4*)(ea + (size_t)e * 8);
        float4 v0 = ap[0], v1 = ap[1];
        a[0] = v0.x; a[1] = v0.y; a[2] = v0.z; a[3] = v0.w;
        a[4] = v1.x; a[5] = v1.y; a[6] = v1.z; a[7] = v1.w;
    } else {
        s = dd = e - NE;
        const float4* ap = (const float4*)(d_mean + (size_t)(e - NE) * 8);
        float4 v0 = ap[0], v1 = ap[1];
        float ic = 1.0f / fmaxf(d_cnt[dd], 1.0f);
        a[0] = v0.x * ic; a[1] = v0.y * ic; a[2] = v0.z * ic; a[3] = v0.w * ic;
        a[4] = v1.x * ic; a[5] = v1.y * ic; a[6] = v1.z * ic; a[7] = v1.w * ic;
    }
    int pos = atomicAdd(&d_cur[dd], 1);
    d_csrc[pos] = s;
#pragma unroll
    for (int l = 0; l < 3; l++) {
        float4 o;
        float* po = (float*)&o;
#pragma unroll
        for (int h = 0; h < 4; h++) {
            float sum = 0.0f;
#pragma unroll
            for (int d = 0; d < 8; d++) sum += a[d] * sw[l * 32 + d * 4 + h];
            po[h] = sum;
        }
        *(float4*)(&d_ale[l][(size_t)pos * 4]) = o;
    }
}

// ---------------- fused: CSR fill (blocks >= PB) + project layer0 (blocks < PB) ----------------
__global__ void k_fillproj(const int* __restrict__ src, const int* __restrict__ dst,
                           const float* __restrict__ ea,
                           const float* __restrict__ X, int fin, const float* __restrict__ W,
                           const float* __restrict__ as_, const float* __restrict__ ad_) {
    __shared__ float sW[64 * 64];
    __shared__ float sx[4 * 64];
    __shared__ float sa[64], sd[64];
    __shared__ float sw[96];
    if (blockIdx.x < PB) {
        project_body(blockIdx.x, PB, X, fin, W, as_, ad_, sW, sx, sa, sd);
        return;
    }
    if (threadIdx.x < 96) sw[threadIdx.x] = d_weatt[threadIdx.x];
    __syncthreads();
    int e = (blockIdx.x - PB) * 256 + threadIdx.x;
    if (e >= ESL) return;
    fill_body(e, src, dst, ea, sw);
}

// ---------------- standalone projection (layers 1,2) ----------------
__global__ void k_project(const float* __restrict__ X, int fin, const float* __restrict__ W,
                          const float* __restrict__ as_, const float* __restrict__ ad_) {
    __shared__ float sW[64 * 64];
    __shared__ float sx[4 * 64];
    __shared__ float sa[64], sd[64];
    project_body(blockIdx.x, gridDim.x, X, fin, W, as_, ad_, sW, sx, sa, sd);
}

// ---------------- fused single-pass softmax-aggregate (precomputed edge logits)
// warp per dst node; lane = h*8+sub owns output cols [2*lane, 2*lane+1].
__global__ void __launch_bounds__(256, 6)
k_agg(const float* __restrict__ ale, const float* __restrict__ b,
      int dorelu, float* __restrict__ out) {
    int tid = threadIdx.x;
    int warp = (blockIdx.x * blockDim.x + tid) >> 5;
    if (warp >= NN) return;
    int lane = tid & 31;
    int h = lane >> 3, sub = lane & 7;
    int beg = d_roff[warp];
    int end = d_roff[warp + 1];
    float ald_h = d_ald[warp * 4 + h];
    float b0 = b[lane * 2], b1 = b[lane * 2 + 1];

    float den = 0.0f, a0 = 0.0f, a1 = 0.0f;
    for (int p0 = beg; p0 < end; p0 += 8) {
        int myp = p0 + sub;
        float c = 0.0f;
        int s = 0;
        if (myp < end) {
            s = d_csrc[myp];
            float alev = ale[(size_t)myp * 4 + h];      // coalesced 128B per batch
            float a = d_als[s * 4 + h] + ald_h + alev;
            float al = a > 0.0f ? a : NEG * a;
            c = __expf(al);                              // alpha O(+-20): no overflow
        }
        // uniform 8-wide: invalid lanes carry c=0 (s=0 gather is L1-hit no-op)
#pragma unroll
        for (int j = 0; j < 8; j++) {
            float cj = __shfl_sync(0xffffffffu, c, h * 8 + j);
            int   sj = __shfl_sync(0xffffffffu, s, j);
            float2 v = *(const float2*)(d_xp + (size_t)sj * 64 + lane * 2);
            den += cj; a0 += cj * v.x; a1 += cj * v.y;
        }
    }
    float inv = 1.0f / (den + 1e-16f);
    float o0 = a0 * inv + b0;
    float o1 = a1 * inv + b1;
    if (dorelu) { o0 = fmaxf(o0, 0.0f); o1 = fmaxf(o1, 0.0f); }
    *(float2*)(out + (size_t)warp * 64 + lane * 2) = make_float2(o0, o1);
}

// ---------------- global mean pool ----------------
__global__ void k_pool(const int* __restrict__ batch, const float* __restrict__ h) {
    size_t t = (size_t)blockIdx.x * blockDim.x + threadIdx.x;
    int n = (int)(t >> 5);
    if (n >= NN) return;
    int c2 = (int)(t & 31) * 2;
    int g = batch[n];
    red2(&d_pool[g * 64 + c2], h[(size_t)n * 64 + c2], h[(size_t)n * 64 + c2 + 1]);
    if (c2 == 0) atomicAdd(&d_gcnt[g], 1.0f);
}

// ---------------- MLP head ----------------
__global__ void k_mlp(const float* __restrict__ fc1w, const float* __restrict__ fc1b,
                      const float* __restrict__ fc2w, const float* __restrict__ fc2b,
                      float* __restrict__ out) {
    int g = threadIdx.x;
    if (g >= NGRAPH) return;
    float ic = 1.0f / fmaxf(d_gcnt[g], 1.0f);
    float hr[64];
#pragma unroll
    for (int c = 0; c < 64; c++) hr[c] = d_pool[g * 64 + c] * ic;
    float y1[32];
#pragma unroll
    for (int j = 0; j < 32; j++) {
        float s = fc1b[j];
#pragma unroll
        for (int c = 0; c < 64; c++) s += hr[c] * fc1w[c * 32 + j];
        y1[j] = fmaxf(s, 0.0f);
    }
#pragma unroll
    for (int o = 0; o < 2; o++) {
        float s = fc2b[o];
#pragma unroll
        for (int j = 0; j < 32; j++) s += y1[j] * fc2w[j * 2 + o];
        out[g * 2 + o] = s;
    }
}

// ---------------- host ----------------
extern "C" void kernel_launch(void* const* d_in, const int* in_sizes, int n_in,
                              void* d_out, int out_size) {
    (void)in_sizes; (void)n_in; (void)out_size;
    const float* x    = (const float*)d_in[0];
    const int*   ei   = (const int*)d_in[1];
    const float* ea   = (const float*)d_in[2];
    const int*   batch= (const int*)d_in[3];
    const float* W0   = (const float*)d_in[4];
    const float* as0  = (const float*)d_in[5];
    const float* ad0  = (const float*)d_in[6];
    const float* We0  = (const float*)d_in[7];
    const float* ae0  = (const float*)d_in[8];
    const float* b0   = (const float*)d_in[9];
    const float* Wh   = (const float*)d_in[10];
    const float* ash  = (const float*)d_in[11];
    const float* adh  = (const float*)d_in[12];
    const float* Weh  = (const float*)d_in[13];
    const float* aeh  = (const float*)d_in[14];
    const float* bh   = (const float*)d_in[15];
    const float* fc1w = (const float*)d_in[16];
    const float* fc1b = (const float*)d_in[17];
    const float* fc2w = (const float*)d_in[18];
    const float* fc2b = (const float*)d_in[19];
    float* out = (float*)d_out;

    const int* src = ei;
    const int* dst = ei + NE;

    void *p_cnt, *p_mean, *p_pool, *p_gcnt, *p_flag, *p_h0, *p_h1, *p_ale;
    cudaGetSymbolAddress(&p_cnt,  d_cnt);
    cudaGetSymbolAddress(&p_mean, d_mean);
    cudaGetSymbolAddress(&p_pool, d_pool);
    cudaGetSymbolAddress(&p_gcnt, d_gcnt);
    cudaGetSymbolAddress(&p_flag, d_flagsum);
    cudaGetSymbolAddress(&p_h0,   d_h0);
    cudaGetSymbolAddress(&p_h1,   d_h1);
    cudaGetSymbolAddress(&p_ale,  d_ale);

    struct LayerCfg {
        const float* X; int fin; const float* W;
        const float* as; const float* ad; const float* b; float* hout; int relu;
    };
    LayerCfg L[3] = {
        { x,            32, W0,        as0,      ad0,      b0,      (float*)p_h0, 1 },
        { (float*)p_h0, 64, Wh,        ash,      adh,      bh,      (float*)p_h1, 0 },
        { (float*)p_h1, 64, Wh + 4096, ash + 64, adh + 64, bh + 64, (float*)p_h0, 0 },
    };

    cudaMemsetAsync(p_cnt,  0, NN * sizeof(float));
    cudaMemsetAsync(p_mean, 0, NN * 8 * sizeof(float));
    cudaMemsetAsync(p_flag, 0, SCB * sizeof(int));
    cudaMemsetAsync(p_pool, 0, NGRAPH * 64 * sizeof(float));
    cudaMemsetAsync(p_gcnt, 0, NGRAPH * sizeof(float));

    // kernel launches: #4 is k_agg layer 0 (ncu capture target)
    k_count<<<(NE + 255) / 256, 256>>>(dst, ea);                                  // 1
    k_scan<<<SCB, 256>>>(We0, ae0, Weh, aeh);                                     // 2
    k_fillproj<<<PB + (ESL + 255) / 256, 256>>>(src, dst, ea,                     // 3
                                                L[0].X, L[0].fin, L[0].W, L[0].as, L[0].ad);
    k_agg<<<(NN * 32 + 255) / 256, 256>>>((const float*)p_ale,                    // 4 <-- profiled
                                          L[0].b, L[0].relu, L[0].hout);
    for (int l = 1; l < 3; l++) {
        k_project<<<1184, 256>>>(L[l].X, L[l].fin, L[l].W, L[l].as, L[l].ad);
        k_agg<<<(NN * 32 + 255) / 256, 256>>>((const float*)p_ale + (size_t)l * ESL * 4,
                                              L[l].b, L[l].relu, L[l].hout);
    }

    k_pool<<<(int)(((size_t)NN * 32 + 255) / 256), 256>>>(batch, (const float*)p_h0);
    k_mlp<<<1, 64>>>(fc1w, fc1b, fc2w, fc2b, out);
}

// round 9
// speedup vs baseline: 1.3850x; 1.0739x over previous
#include <cuda_runtime.h>
#include <math.h>

#define NN 100000
#define NE 1600000
#define ESL (NE + NN)
#define NGRAPH 64
#define NEG 0.2f
#define SCB 196          // ceil(NN / 512) scan blocks
#define PB  1184         // project blocks inside fused fill2+proj kernel

// ---------------- scratch (device globals; no allocation) ----------------
__device__ float    d_cnt[NN];
__device__ float    d_mean[NN * 8];
__device__ float    d_xp[NN * 64];
__device__ float    d_als[NN * 4];
__device__ float    d_ald[NN * 4];
__device__ float    d_h0[NN * 64];
__device__ float    d_h1[NN * 64];
__device__ float    d_pool[NGRAPH * 64];
__device__ float    d_gcnt[NGRAPH];
__device__ float    d_weatt[3 * 32];
// CSR
__device__ int      d_roff[NN + 1];
__device__ int      d_cur[NN];
__device__ int      d_eid[ESL];                 // CSR slot -> original edge id
__device__ int      d_csrc[ESL];                // CSR slot -> src node (coalesced write)
__device__ float    d_ale[3][(size_t)ESL * 4];  // per-layer edge logits (coalesced write)
__device__ int      d_flagsum[SCB];             // lookback: 0 = not ready, else localsum+1

// ---------------- helpers ----------------
__device__ __forceinline__ void red2(float* p, float a, float b) {
    asm volatile("red.global.add.v2.f32 [%0], {%1, %2};" :: "l"(p), "f"(a), "f"(b) : "memory");
}

// ---------------- self-loop mean edge-attr (sum) + in-degree count ----------------
__global__ void k_count(const int* __restrict__ dst, const float* __restrict__ ea) {
    int e = blockIdx.x * blockDim.x + threadIdx.x;
    if (e >= NE) return;
    int dd = dst[e];
    atomicAdd(&d_cnt[dd], 1.0f);
#pragma unroll
    for (int d = 0; d < 8; d += 2)
        red2(&d_mean[dd * 8 + d], ea[(size_t)e * 8 + d], ea[(size_t)e * 8 + d + 1]);
}

// ---------------- one-kernel scan (decoupled lookback) + weatt + roff[NN] ----------------
__global__ void k_scan(const float* __restrict__ We0, const float* __restrict__ ae0,
                       const float* __restrict__ Weh, const float* __restrict__ aeh) {
    __shared__ int sh[256];
    __shared__ int sp[256];
    int t = threadIdx.x, bid = blockIdx.x;
    int nb = bid * 512 + t * 2;
    int d0 = 0, d1 = 0;
    if (nb < NN) {                      // NN even -> nb+1 < NN too
        float2 c = *(const float2*)&d_cnt[nb];
        d0 = (int)(c.x + 0.5f) + 1;
        d1 = (int)(c.y + 0.5f) + 1;
    }
    sh[t] = d0 + d1;
    __syncthreads();
#pragma unroll
    for (int off = 1; off < 256; off <<= 1) {
        int v = (t >= off) ? sh[t - off] : 0;
        __syncthreads();
        sh[t] += v;
        __syncthreads();
    }
    int total = sh[255];
    if (t == 0) {
        __threadfence();
        atomicExch(&d_flagsum[bid], total + 1);
    }
    int pre = 0;
    if (t < bid) {
        volatile int* f = &d_flagsum[t];
        int x;
        while ((x = *f) == 0) { }
        pre = x - 1;
    }
    sp[t] = pre;
    __syncthreads();
#pragma unroll
    for (int off = 128; off; off >>= 1) {
        if (t < off) sp[t] += sp[t + off];
        __syncthreads();
    }
    int base = sp[0];
    int off0 = base + sh[t] - (d0 + d1);
    if (nb < NN) {
        d_roff[nb] = off0;          d_cur[nb] = off0;
        d_roff[nb + 1] = off0 + d0; d_cur[nb + 1] = off0 + d0;
    }
    if (bid == 0) {
        if (t < 96) {
            int l = t >> 5, r = t & 31;
            int d = r >> 2, h = r & 3;
            const float* We = (l == 0) ? We0 : (Weh + (l - 1) * 512);
            const float* ae = (l == 0) ? ae0 : (aeh + (l - 1) * 64);
            float s = 0.0f;
#pragma unroll
            for (int c = 0; c < 16; c++) s += We[d * 64 + h * 16 + c] * ae[h * 16 + c];
            d_weatt[l * 32 + d * 4 + h] = s;
        }
        if (t == 0) d_roff[NN] = ESL;
    }
}

// ---------------- fill pass 1: permutation only (one 4B scattered store per edge) ----------------
__global__ void k_fill1(const int* __restrict__ dst) {
    int e = blockIdx.x * blockDim.x + threadIdx.x;
    if (e >= ESL) return;
    int dd = (e < NE) ? dst[e] : e - NE;
    int pos = atomicAdd(&d_cur[dd], 1);
    d_eid[pos] = e;
}

// ---------------- projection body: xp = X @ W ; al_s/al_d per (node, head) ----------------
__device__ __forceinline__ void project_body(
        int bid, int nblocks,
        const float* __restrict__ X, int fin, const float* __restrict__ W,
        const float* __restrict__ as_, const float* __restrict__ ad_,
        float* sW, float* sx, float* sa, float* sd) {
    int tid = threadIdx.x;
    for (int i = tid; i < fin * 64; i += 256) sW[i] = W[i];
    if (tid < 64) { sa[tid] = as_[tid]; sd[tid] = ad_[tid]; }
    __syncthreads();
    int slot = tid >> 6, col = tid & 63;
    for (int base = bid * 4; base < NN; base += nblocks * 4) {
        int n = base + slot;
        if (n < NN && col < fin) sx[slot * 64 + col] = X[(size_t)n * fin + col];
        __syncthreads();
        if (n < NN) {
            float acc = 0.0f;
#pragma unroll 4
            for (int i = 0; i < fin; i += 4) {
                float4 xv = *(const float4*)(sx + slot * 64 + i);
                acc += xv.x * sW[(i + 0) * 64 + col];
                acc += xv.y * sW[(i + 1) * 64 + col];
                acc += xv.z * sW[(i + 2) * 64 + col];
                acc += xv.w * sW[(i + 3) * 64 + col];
            }
            d_xp[(size_t)n * 64 + col] = acc;
            float ps = acc * sa[col], pd = acc * sd[col];
#pragma unroll
            for (int off = 8; off; off >>= 1) {
                ps += __shfl_xor_sync(0xffffffffu, ps, off);
                pd += __shfl_xor_sync(0xffffffffu, pd, off);
            }
            if ((col & 15) == 0) {
                int h = col >> 4;
                d_als[n * 4 + h] = ps;
                d_ald[n * 4 + h] = pd;
            }
        }
        __syncthreads();
    }
}

// ---------------- fill pass 2: thread = CSR slot; gather-compute, coalesced writes ----------------
__device__ __forceinline__ void fill2_body(int slot, const int* __restrict__ src,
                                           const float* __restrict__ ea, const float* sw) {
    int e = d_eid[slot];                 // coalesced
    int s;
    float a[8];
    if (e < NE) {
        s = src[e];                      // scattered 4B read (clean sector fetch)
        const float4* ap = (const float4*)(ea + (size_t)e * 8);  // scattered 32B read
        float4 v0 = ap[0], v1 = ap[1];
        a[0] = v0.x; a[1] = v0.y; a[2] = v0.z; a[3] = v0.w;
        a[4] = v1.x; a[5] = v1.y; a[6] = v1.z; a[7] = v1.w;
    } else {
        int n = e - NE;
        s = n;
        const float4* ap = (const float4*)(d_mean + (size_t)n * 8);
        float4 v0 = ap[0], v1 = ap[1];
        float ic = 1.0f / fmaxf(d_cnt[n], 1.0f);
        a[0] = v0.x * ic; a[1] = v0.y * ic; a[2] = v0.z * ic; a[3] = v0.w * ic;
        a[4] = v1.x * ic; a[5] = v1.y * ic; a[6] = v1.z * ic; a[7] = v1.w * ic;
    }
    d_csrc[slot] = s;                    // coalesced
#pragma unroll
    for (int l = 0; l < 3; l++) {
        float4 o;
        float* po = (float*)&o;
#pragma unroll
        for (int h = 0; h < 4; h++) {
            float sum = 0.0f;
#pragma unroll
            for (int d = 0; d < 8; d++) sum += a[d] * sw[l * 32 + d * 4 + h];
            po[h] = sum;
        }
        *(float4*)(&d_ale[l][(size_t)slot * 4]) = o;   // coalesced 16B
    }
}

// ---------------- fused: fill2 (blocks >= PB) + project layer0 (blocks < PB) ----------------
__global__ void k_fill2proj(const int* __restrict__ src, const float* __restrict__ ea,
                            const float* __restrict__ X, int fin, const float* __restrict__ W,
                            const float* __restrict__ as_, const float* __restrict__ ad_) {
    __shared__ float sW[64 * 64];
    __shared__ float sx[4 * 64];
    __shared__ float sa[64], sd[64];
    __shared__ float sw[96];
    if (blockIdx.x < PB) {
        project_body(blockIdx.x, PB, X, fin, W, as_, ad_, sW, sx, sa, sd);
        return;
    }
    if (threadIdx.x < 96) sw[threadIdx.x] = d_weatt[threadIdx.x];
    __syncthreads();
    int slot = (blockIdx.x - PB) * 256 + threadIdx.x;
    if (slot >= ESL) return;
    fill2_body(slot, src, ea, sw);
}

// ---------------- standalone projection (layers 1,2) ----------------
__global__ void k_project(const float* __restrict__ X, int fin, const float* __restrict__ W,
                          const float* __restrict__ as_, const float* __restrict__ ad_) {
    __shared__ float sW[64 * 64];
    __shared__ float sx[4 * 64];
    __shared__ float sa[64], sd[64];
    project_body(blockIdx.x, gridDim.x, X, fin, W, as_, ad_, sW, sx, sa, sd);
}

// ---------------- fused single-pass softmax-aggregate (precomputed edge logits)
// warp per dst node; lane = h*8+sub owns output cols [2*lane, 2*lane+1].
__global__ void __launch_bounds__(256, 6)
k_agg(const float* __restrict__ ale, const float* __restrict__ b,
      int dorelu, float* __restrict__ out) {
    int tid = threadIdx.x;
    int warp = (blockIdx.x * blockDim.x + tid) >> 5;
    if (warp >= NN) return;
    int lane = tid & 31;
    int h = lane >> 3, sub = lane & 7;
    int beg = d_roff[warp];
    int end = d_roff[warp + 1];
    float ald_h = d_ald[warp * 4 + h];
    float b0 = b[lane * 2], b1 = b[lane * 2 + 1];

    float den = 0.0f, a0 = 0.0f, a1 = 0.0f;
    for (int p0 = beg; p0 < end; p0 += 8) {
        int myp = p0 + sub;
        float c = 0.0f;
        int s = 0;
        if (myp < end) {
            s = d_csrc[myp];
            float alev = ale[(size_t)myp * 4 + h];      // coalesced 128B per batch
            float a = d_als[s * 4 + h] + ald_h + alev;
            float al = a > 0.0f ? a : NEG * a;
            c = __expf(al);                              // alpha O(+-20): no overflow
        }
#pragma unroll
        for (int j = 0; j < 8; j++) {
            float cj = __shfl_sync(0xffffffffu, c, h * 8 + j);
            int   sj = __shfl_sync(0xffffffffu, s, j);
            float2 v = *(const float2*)(d_xp + (size_t)sj * 64 + lane * 2);
            den += cj; a0 += cj * v.x; a1 += cj * v.y;
        }
    }
    float inv = 1.0f / (den + 1e-16f);
    float o0 = a0 * inv + b0;
    float o1 = a1 * inv + b1;
    if (dorelu) { o0 = fmaxf(o0, 0.0f); o1 = fmaxf(o1, 0.0f); }
    *(float2*)(out + (size_t)warp * 64 + lane * 2) = make_float2(o0, o1);
}

// ---------------- global mean pool ----------------
__global__ void k_pool(const int* __restrict__ batch, const float* __restrict__ h) {
    size_t t = (size_t)blockIdx.x * blockDim.x + threadIdx.x;
    int n = (int)(t >> 5);
    if (n >= NN) return;
    int c2 = (int)(t & 31) * 2;
    int g = batch[n];
    red2(&d_pool[g * 64 + c2], h[(size_t)n * 64 + c2], h[(size_t)n * 64 + c2 + 1]);
    if (c2 == 0) atomicAdd(&d_gcnt[g], 1.0f);
}

// ---------------- MLP head ----------------
__global__ void k_mlp(const float* __restrict__ fc1w, const float* __restrict__ fc1b,
                      const float* __restrict__ fc2w, const float* __restrict__ fc2b,
                      float* __restrict__ out) {
    int g = threadIdx.x;
    if (g >= NGRAPH) return;
    float ic = 1.0f / fmaxf(d_gcnt[g], 1.0f);
    float hr[64];
#pragma unroll
    for (int c = 0; c < 64; c++) hr[c] = d_pool[g * 64 + c] * ic;
    float y1[32];
#pragma unroll
    for (int j = 0; j < 32; j++) {
        float s = fc1b[j];
#pragma unroll
        for (int c = 0; c < 64; c++) s += hr[c] * fc1w[c * 32 + j];
        y1[j] = fmaxf(s, 0.0f);
    }
#pragma unroll
    for (int o = 0; o < 2; o++) {
        float s = fc2b[o];
#pragma unroll
        for (int j = 0; j < 32; j++) s += y1[j] * fc2w[j * 2 + o];
        out[g * 2 + o] = s;
    }
}

// ---------------- host ----------------
extern "C" void kernel_launch(void* const* d_in, const int* in_sizes, int n_in,
                              void* d_out, int out_size) {
    (void)in_sizes; (void)n_in; (void)out_size;
    const float* x    = (const float*)d_in[0];
    const int*   ei   = (const int*)d_in[1];
    const float* ea   = (const float*)d_in[2];
    const int*   batch= (const int*)d_in[3];
    const float* W0   = (const float*)d_in[4];
    const float* as0  = (const float*)d_in[5];
    const float* ad0  = (const float*)d_in[6];
    const float* We0  = (const float*)d_in[7];
    const float* ae0  = (const float*)d_in[8];
    const float* b0   = (const float*)d_in[9];
    const float* Wh   = (const float*)d_in[10];
    const float* ash  = (const float*)d_in[11];
    const float* adh  = (const float*)d_in[12];
    const float* Weh  = (const float*)d_in[13];
    const float* aeh  = (const float*)d_in[14];
    const float* bh   = (const float*)d_in[15];
    const float* fc1w = (const float*)d_in[16];
    const float* fc1b = (const float*)d_in[17];
    const float* fc2w = (const float*)d_in[18];
    const float* fc2b = (const float*)d_in[19];
    float* out = (float*)d_out;

    const int* src = ei;
    const int* dst = ei + NE;

    void *p_cnt, *p_mean, *p_pool, *p_gcnt, *p_flag, *p_h0, *p_h1, *p_ale;
    cudaGetSymbolAddress(&p_cnt,  d_cnt);
    cudaGetSymbolAddress(&p_mean, d_mean);
    cudaGetSymbolAddress(&p_pool, d_pool);
    cudaGetSymbolAddress(&p_gcnt, d_gcnt);
    cudaGetSymbolAddress(&p_flag, d_flagsum);
    cudaGetSymbolAddress(&p_h0,   d_h0);
    cudaGetSymbolAddress(&p_h1,   d_h1);
    cudaGetSymbolAddress(&p_ale,  d_ale);

    struct LayerCfg {
        const float* X; int fin; const float* W;
        const float* as; const float* ad; const float* b; float* hout; int relu;
    };
    LayerCfg L[3] = {
        { x,            32, W0,        as0,      ad0,      b0,      (float*)p_h0, 1 },
        { (float*)p_h0, 64, Wh,        ash,      adh,      bh,      (float*)p_h1, 0 },
        { (float*)p_h1, 64, Wh + 4096, ash + 64, adh + 64, bh + 64, (float*)p_h0, 0 },
    };

    cudaMemsetAsync(p_cnt,  0, NN * sizeof(float));
    cudaMemsetAsync(p_mean, 0, NN * 8 * sizeof(float));
    cudaMemsetAsync(p_flag, 0, SCB * sizeof(int));
    cudaMemsetAsync(p_pool, 0, NGRAPH * 64 * sizeof(float));
    cudaMemsetAsync(p_gcnt, 0, NGRAPH * sizeof(float));

    // kernel launches: #4 is the fused fill2+proj0 (ncu capture target)
    k_count<<<(NE + 255) / 256, 256>>>(dst, ea);                                  // 1
    k_scan<<<SCB, 256>>>(We0, ae0, Weh, aeh);                                     // 2
    k_fill1<<<(ESL + 255) / 256, 256>>>(dst);                                     // 3
    k_fill2proj<<<PB + (ESL + 255) / 256, 256>>>(src, ea,                         // 4 <-- profiled
                                                 L[0].X, L[0].fin, L[0].W, L[0].as, L[0].ad);
    k_agg<<<(NN * 32 + 255) / 256, 256>>>((const float*)p_ale,                    // 5
                                          L[0].b, L[0].relu, L[0].hout);
    for (int l = 1; l < 3; l++) {
        k_project<<<1184, 256>>>(L[l].X, L[l].fin, L[l].W, L[l].as, L[l].ad);
        k_agg<<<(NN * 32 + 255) / 256, 256>>>((const float*)p_ale + (size_t)l * ESL * 4,
                                              L[l].b, L[l].relu, L[l].hout);
    }

    k_pool<<<(int)(((size_t)NN * 32 + 255) / 256), 256>>>(batch, (const float*)p_h0);
    k_mlp<<<1, 64>>>(fc1w, fc1b, fc2w, fc2b, out);
}